// round 3
// baseline (speedup 1.0000x reference)
#include <cuda_runtime.h>
#include <mma.h>
#include <cstdint>
#include <cstddef>

using namespace nvcuda;

#define BATCH 8192
#define FDIM  1024
#define HDIM  256
#define NTASK 8

// ---------------- scratch (static device globals; no allocation) ----------------
__device__ float    g_h[BATCH * HDIM];        // pre-activation h
__device__ float    g_G[HDIM * HDIM];         // Gram = W1 @ W1^T
__device__ float    g_coeffs[BATCH * NTASK];
__device__ float    g_unc2[BATCH * NTASK];
__device__ unsigned g_max2bits;
__device__ float    g_gated[BATCH * NTASK];
__device__ float    g_x0[BATCH * FDIM];
__device__ float    g_x1[BATCH * FDIM];

// ---------------- cp.async helpers ----------------
__device__ __forceinline__ void cp16(float* s, const float* g) {
    unsigned sa = (unsigned)__cvta_generic_to_shared(s);
    asm volatile("cp.async.cg.shared.global [%0], [%1], 16;" :: "r"(sa), "l"(g));
}
__device__ __forceinline__ void cp_commit() {
    asm volatile("cp.async.commit_group;");
}
template <int N>
__device__ __forceinline__ void cp_wait() {
    asm volatile("cp.async.wait_group %0;" :: "n"(N));
}

// ---------------- WMMA tf32 GEMM, 128x128x32 tiles, 256 threads, double-buffered ----------------
// THREE: 3xTF32 error-compensated (fp32-accurate). BCOL: Bm given as [N,K] row-major
// (logical B = Bm^T). EPI: 0 = plain store, 1 = +bias[col], 2 = resid + gate*acc.
constexpr int BM = 128, BN = 128, BK = 32;
constexpr int ALD = BK + 4;                       // 36
constexpr int ASZ = BM * ALD;                     // 4608 floats

template <bool THREE, bool BCOL, int EPI>
__global__ void __launch_bounds__(256) gemm128(
    const float* __restrict__ A, int lda,
    const float* __restrict__ Bm, int ldb,
    float* __restrict__ C, int ldc,
    int Kdim,
    const float* __restrict__ bias,
    const float* __restrict__ resid,
    const float* __restrict__ gate, int gcol)
{
    constexpr int BLD = BCOL ? (BK + 4) : (BN + 4);                 // 36 or 132
    constexpr int BSZ = BCOL ? (BN * (BK + 4)) : (BK * (BN + 4));   // floats
    constexpr int STAGE = ASZ + BSZ;

    extern __shared__ float smem[];

    const int tid = threadIdx.x;
    const int m0 = blockIdx.y * BM;
    const int n0 = blockIdx.x * BN;
    const int warp = tid >> 5;
    const int wm = warp & 3;      // 0..3 -> 32-row slice
    const int wn = warp >> 2;     // 0..1 -> 64-col slice

    wmma::fragment<wmma::accumulator, 16, 16, 8, float> acc[2][4];
#pragma unroll
    for (int i = 0; i < 2; i++)
#pragma unroll
        for (int j = 0; j < 4; j++) wmma::fill_fragment(acc[i][j], 0.0f);

    const int iters = Kdim / BK;

    auto load_tiles = [&](int s, int k0) {
        float* as = smem + s * STAGE;
        float* bs = as + ASZ;
#pragma unroll
        for (int it = 0; it < 4; it++) {
            int e = it * 256 + tid;
            int r = e >> 3, c = (e & 7) << 2;
            cp16(&as[r * ALD + c], &A[(size_t)(m0 + r) * lda + k0 + c]);
        }
        if (BCOL) {
#pragma unroll
            for (int it = 0; it < 4; it++) {
                int e = it * 256 + tid;
                int r = e >> 3, c = (e & 7) << 2;
                cp16(&bs[r * BLD + c], &Bm[(size_t)(n0 + r) * ldb + k0 + c]);
            }
        } else {
#pragma unroll
            for (int it = 0; it < 4; it++) {
                int e = it * 256 + tid;
                int r = e >> 5, c = (e & 31) << 2;
                cp16(&bs[r * BLD + c], &Bm[(size_t)(k0 + r) * ldb + n0 + c]);
            }
        }
    };

    load_tiles(0, 0);
    cp_commit();

    for (int it = 0; it < iters; it++) {
        if (it + 1 < iters) load_tiles((it + 1) & 1, (it + 1) * BK);
        cp_commit();                // empty group on last iter keeps count aligned
        cp_wait<1>();
        __syncthreads();

        const float* as = smem + (it & 1) * STAGE;
        const float* bs = as + ASZ;

#pragma unroll
        for (int kk = 0; kk < BK / 8; kk++) {
            wmma::fragment<wmma::matrix_a, 16, 16, 8, wmma::precision::tf32, wmma::row_major> ah[2], al[2];
#pragma unroll
            for (int i = 0; i < 2; i++) {
                wmma::load_matrix_sync(ah[i], &as[(wm * 32 + i * 16) * ALD + kk * 8], ALD);
                if (THREE) {
#pragma unroll
                    for (int e = 0; e < ah[i].num_elements; e++) {
                        float v = ah[i].x[e];
                        float hi = wmma::__float_to_tf32(v);
                        al[i].x[e] = wmma::__float_to_tf32(v - hi);
                        ah[i].x[e] = hi;
                    }
                } else {
#pragma unroll
                    for (int e = 0; e < ah[i].num_elements; e++)
                        ah[i].x[e] = wmma::__float_to_tf32(ah[i].x[e]);
                }
            }
            if constexpr (BCOL) {
                wmma::fragment<wmma::matrix_b, 16, 16, 8, wmma::precision::tf32, wmma::col_major> bh[4], bl[4];
#pragma unroll
                for (int j = 0; j < 4; j++) {
                    wmma::load_matrix_sync(bh[j], &bs[(wn * 64 + j * 16) * BLD + kk * 8], BLD);
                    if (THREE) {
#pragma unroll
                        for (int e = 0; e < bh[j].num_elements; e++) {
                            float v = bh[j].x[e];
                            float hi = wmma::__float_to_tf32(v);
                            bl[j].x[e] = wmma::__float_to_tf32(v - hi);
                            bh[j].x[e] = hi;
                        }
                    } else {
#pragma unroll
                        for (int e = 0; e < bh[j].num_elements; e++)
                            bh[j].x[e] = wmma::__float_to_tf32(bh[j].x[e]);
                    }
                }
#pragma unroll
                for (int i = 0; i < 2; i++)
#pragma unroll
                    for (int j = 0; j < 4; j++) {
                        if (THREE) {
                            wmma::mma_sync(acc[i][j], al[i], bh[j], acc[i][j]);
                            wmma::mma_sync(acc[i][j], ah[i], bl[j], acc[i][j]);
                        }
                        wmma::mma_sync(acc[i][j], ah[i], bh[j], acc[i][j]);
                    }
            } else {
                wmma::fragment<wmma::matrix_b, 16, 16, 8, wmma::precision::tf32, wmma::row_major> bh[4], bl[4];
#pragma unroll
                for (int j = 0; j < 4; j++) {
                    wmma::load_matrix_sync(bh[j], &bs[(kk * 8) * BLD + wn * 64 + j * 16], BLD);
                    if (THREE) {
#pragma unroll
                        for (int e = 0; e < bh[j].num_elements; e++) {
                            float v = bh[j].x[e];
                            float hi = wmma::__float_to_tf32(v);
                            bl[j].x[e] = wmma::__float_to_tf32(v - hi);
                            bh[j].x[e] = hi;
                        }
                    } else {
#pragma unroll
                        for (int e = 0; e < bh[j].num_elements; e++)
                            bh[j].x[e] = wmma::__float_to_tf32(bh[j].x[e]);
                    }
                }
#pragma unroll
                for (int i = 0; i < 2; i++)
#pragma unroll
                    for (int j = 0; j < 4; j++) {
                        if (THREE) {
                            wmma::mma_sync(acc[i][j], al[i], bh[j], acc[i][j]);
                            wmma::mma_sync(acc[i][j], ah[i], bl[j], acc[i][j]);
                        }
                        wmma::mma_sync(acc[i][j], ah[i], bh[j], acc[i][j]);
                    }
            }
        }
        __syncthreads();   // all warps done with this stage before it is overwritten
    }

    // epilogue: stage accumulators to smem (reuse pipeline buffers), write float4
    constexpr int SLD = BN + 4;     // 132
    float* St = smem;
#pragma unroll
    for (int i = 0; i < 2; i++)
#pragma unroll
        for (int j = 0; j < 4; j++)
            wmma::store_matrix_sync(&St[(wm * 32 + i * 16) * SLD + wn * 64 + j * 16],
                                    acc[i][j], SLD, wmma::mem_row_major);
    __syncthreads();
#pragma unroll
    for (int it = 0; it < 16; it++) {
        int e = it * 256 + tid;
        int r = e >> 5, c = (e & 31) << 2;
        float4 v = *(const float4*)&St[r * SLD + c];
        int row = m0 + r, col = n0 + c;
        if (EPI == 1) {
            v.x += bias[col]; v.y += bias[col + 1]; v.z += bias[col + 2]; v.w += bias[col + 3];
        } else if (EPI == 2) {
            float g = gate[row * NTASK + gcol];
            float4 rs = *(const float4*)&resid[(size_t)row * ldc + col];
            v.x = rs.x + g * v.x; v.y = rs.y + g * v.y;
            v.z = rs.z + g * v.z; v.w = rs.w + g * v.w;
        }
        *(float4*)&C[(size_t)row * ldc + col] = v;
    }
}

// ---------------- coeffs = relu(h) @ W2^T + b2 ----------------
__global__ void coeffs_kernel(const float* __restrict__ W2, const float* __restrict__ b2)
{
    int tid = threadIdx.x;
    int row = blockIdx.x * 32 + (tid >> 3);
    int k = tid & 7;
    const float* hr = g_h + (size_t)row * HDIM;
    const float* w = W2 + k * HDIM;
    float s = b2[k];
#pragma unroll 8
    for (int h = 0; h < HDIM; h++) s += fmaxf(hr[h], 0.0f) * w[h];
    g_coeffs[row * NTASK + k] = s;
}

// ---------------- init global max ----------------
__global__ void init_kernel() { g_max2bits = 0u; }

// ---------------- unc^2[b,k] = a^T G a,  a[h] = W2[k,h] * (h[b,h] > 0) ----------------
__global__ void __launch_bounds__(256) unc_kernel(const float* __restrict__ W2)
{
    __shared__ float W2s[NTASK * HDIM];
    __shared__ float Gs[HDIM * 32];
    int tid = threadIdx.x, lane = tid & 31, warp = tid >> 5;
    for (int i = tid; i < NTASK * HDIM; i += 256) W2s[i] = W2[i];

    int row = blockIdx.x * 8 + warp;
    const float* hr = g_h + (size_t)row * HDIM;
    unsigned mb[8];
#pragma unroll
    for (int j = 0; j < 8; j++)
        mb[j] = __ballot_sync(0xffffffffu, hr[j * 32 + lane] > 0.0f);

    float u2[8];
#pragma unroll
    for (int k = 0; k < 8; k++) u2[k] = 0.0f;

    for (int c = 0; c < 8; c++) {
        __syncthreads();
        for (int i = tid; i < HDIM * 32; i += 256) {
            int h = i >> 5, l = i & 31;
            Gs[i] = g_G[h * HDIM + c * 32 + l];
        }
        __syncthreads();
        float t[8];
#pragma unroll
        for (int k = 0; k < 8; k++) t[k] = 0.0f;
        for (int h = 0; h < HDIM; h++) {
            if ((mb[h >> 5] >> (h & 31)) & 1u) {     // warp-uniform branch
                float gv = Gs[h * 32 + lane];
#pragma unroll
                for (int k = 0; k < 8; k++) t[k] += W2s[k * HDIM + h] * gv;
            }
        }
        int hp = c * 32 + lane;
        if ((mb[hp >> 5] >> (hp & 31)) & 1u) {
#pragma unroll
            for (int k = 0; k < 8; k++) u2[k] += W2s[k * HDIM + hp] * t[k];
        }
    }
#pragma unroll
    for (int k = 0; k < 8; k++) {
        float v = u2[k];
        for (int off = 16; off; off >>= 1) v += __shfl_down_sync(0xffffffffu, v, off);
        if (lane == 0) {
            v = fmaxf(v, 0.0f);
            g_unc2[row * NTASK + k] = v;
            atomicMax(&g_max2bits, __float_as_uint(v));
        }
    }
}

// ---------------- gating ----------------
__global__ void gate_kernel(const float* __restrict__ bthr, const float* __restrict__ beta)
{
    int i = blockIdx.x * blockDim.x + threadIdx.x;
    if (i >= BATCH * NTASK) return;
    float max2 = __uint_as_float(g_max2bits);
    float u = (max2 > 0.0f) ? sqrtf(g_unc2[i] / max2) : sqrtf(g_unc2[i]);
    float base = log1pf(expf(bthr[0]));          // softplus
    float thr = base * (1.0f + fmaxf(beta[0], 0.0f) * u);
    float cf = g_coeffs[i];
    g_gated[i] = (fabsf(cf) < thr) ? 0.0f : cf;
}

// ---------------- launch ----------------
extern "C" void kernel_launch(void* const* d_in, const int* in_sizes, int n_in,
                              void* d_out, int out_size)
{
    const float* features = (const float*)d_in[0];
    const float* W1   = (const float*)d_in[1];
    const float* b1   = (const float*)d_in[2];
    const float* W2   = (const float*)d_in[3];
    const float* b2   = (const float*)d_in[4];
    const float* task = (const float*)d_in[5];
    const float* projW = (const float*)d_in[6];
    const float* bthr = (const float*)d_in[7];
    const float* beta = (const float*)d_in[8];
    float* out = (float*)d_out;

    float *hbuf, *Gbuf, *x0, *x1, *gated;
    cudaGetSymbolAddress((void**)&hbuf, g_h);
    cudaGetSymbolAddress((void**)&Gbuf, g_G);
    cudaGetSymbolAddress((void**)&x0, g_x0);
    cudaGetSymbolAddress((void**)&x1, g_x1);
    cudaGetSymbolAddress((void**)&gated, g_gated);

    // dynamic smem sizes (floats): 2 * (ASZ + BSZ)
    const int smem_bcol = 2 * (ASZ + BN * (BK + 4)) * 4;        // 73728 B
    const int smem_brow = 2 * (ASZ + BK * (BN + 4)) * 4;        // 70656 B

    cudaFuncSetAttribute(gemm128<true,  true,  1>, cudaFuncAttributeMaxDynamicSharedMemorySize, smem_bcol);
    cudaFuncSetAttribute(gemm128<true,  true,  0>, cudaFuncAttributeMaxDynamicSharedMemorySize, smem_bcol);
    cudaFuncSetAttribute(gemm128<false, false, 2>, cudaFuncAttributeMaxDynamicSharedMemorySize, smem_brow);

    dim3 blk(256);

    // h = F @ W1^T + b1   (3xTF32: mask-accurate)
    gemm128<true, true, 1><<<dim3(HDIM / BN, BATCH / BM), blk, smem_bcol>>>(
        features, FDIM, W1, FDIM, hbuf, HDIM, FDIM, b1, nullptr, nullptr, 0);

    // G = W1 @ W1^T       (3xTF32)
    gemm128<true, true, 0><<<dim3(HDIM / BN, HDIM / BM), blk, smem_bcol>>>(
        W1, FDIM, W1, FDIM, Gbuf, HDIM, FDIM, nullptr, nullptr, nullptr, 0);

    coeffs_kernel<<<BATCH / 32, 256>>>(W2, b2);
    init_kernel<<<1, 1>>>();
    unc_kernel<<<BATCH / 8, 256>>>(W2);
    gate_kernel<<<(BATCH * NTASK + 255) / 256, 256>>>(bthr, beta);

    // sequential task-vector chain (1xTF32, corrections only)
    const float* xin = features;
    float* xout = x0;
    for (int j = 0; j < NTASK; j++) {
        gemm128<false, false, 2><<<dim3(FDIM / BN, BATCH / BM), blk, smem_brow>>>(
            xin, FDIM, task + (size_t)j * FDIM * FDIM, FDIM,
            xout, FDIM, FDIM, nullptr, xin, gated, j);
        xin = xout;
        xout = (xout == x0) ? x1 : x0;
    }

    // out = x @ proj_W^T  (3xTF32: proj ~ identity, must not truncate x)
    gemm128<true, true, 0><<<dim3(FDIM / BN, BATCH / BM), blk, smem_bcol>>>(
        xin, FDIM, projW, FDIM, out, FDIM, FDIM, nullptr, nullptr, nullptr, 0);
}

// round 5
// speedup vs baseline: 1.0660x; 1.0660x over previous
#include <cuda_runtime.h>
#include <mma.h>
#include <cstdint>
#include <cstddef>

using namespace nvcuda;

#define BATCH 8192
#define FDIM  1024
#define HDIM  256
#define NTASK 8

// ---------------- scratch (static device globals; no allocation) ----------------
// tf32-rounded hi/lo split operands (fp32 storage, tf32-exact values)
__device__ float g_fhi[BATCH * FDIM], g_flo[BATCH * FDIM];   // features split; reused as x split for proj
__device__ float g_W1hi[HDIM * FDIM], g_W1lo[HDIM * FDIM];
__device__ float g_Thi[NTASK * FDIM * FDIM];                 // task mats, transposed to [N,K], tf32 (1-term chain)
__device__ float g_Phi[FDIM * FDIM], g_Plo[FDIM * FDIM];     // projW split ([N,K] already)
// chain ping-pong: full-precision x and tf32-rounded copy (A operand)
__device__ float g_xa[BATCH * FDIM], g_xar[BATCH * FDIM];
__device__ float g_xb[BATCH * FDIM], g_xbr[BATCH * FDIM];
__device__ float    g_h[BATCH * HDIM];
__device__ float    g_G[HDIM * HDIM];
__device__ float    g_coeffs[BATCH * NTASK];
__device__ float    g_unc2[BATCH * NTASK];
__device__ unsigned g_max2bits;
__device__ float    g_gated[BATCH * NTASK];

// ---------------- cp.async helpers ----------------
__device__ __forceinline__ void cp16(float* s, const float* g) {
    unsigned sa = (unsigned)__cvta_generic_to_shared(s);
    asm volatile("cp.async.cg.shared.global [%0], [%1], 16;" :: "r"(sa), "l"(g));
}
__device__ __forceinline__ void cp_commit() { asm volatile("cp.async.commit_group;"); }
template <int N> __device__ __forceinline__ void cp_wait() {
    asm volatile("cp.async.wait_group %0;" :: "n"(N));
}

// ---------------- tf32 GEMM: C[M,N] = A[M,K] @ B[N,K]^T ----------------
// Operands are PRE-ROUNDED to tf32 values (prep kernels) -> no cvt in inner loop.
// 128x64x32 tiles, 128 threads (4 warps, 64x32 warp tiles), cp.async double buffer.
// EPI: 0 = store, 1 = +bias[col] store, 2 = C += acc, 3 = chain (resid + gate*acc -> C, tf32(C) -> Cr)
constexpr int BM = 128, BN = 64, BK = 32;
constexpr int ALD = BK + 4;                 // 36
constexpr int ASZ = BM * ALD;               // 4608
constexpr int BSZ = BN * ALD;               // 2304
constexpr int STAGE = ASZ + BSZ;            // 6912 floats

template <int EPI>
__global__ void __launch_bounds__(128) gemm_tf32(
    const float* __restrict__ A, int lda,
    const float* __restrict__ Bm, int ldb,     // [N, K] row-major
    float* __restrict__ C, int ldc, int Kdim,
    const float* __restrict__ bias,
    const float* __restrict__ resid,
    const float* __restrict__ gate, int gcol,
    float* __restrict__ Cr)
{
    extern __shared__ float smem[];

    const int tid = threadIdx.x;
    const int m0 = blockIdx.y * BM;
    const int n0 = blockIdx.x * BN;
    const int warp = tid >> 5;
    const int wm = warp >> 1;     // 0..1 -> 64-row slice
    const int wn = warp & 1;      // 0..1 -> 32-col slice

    wmma::fragment<wmma::accumulator, 16, 16, 8, float> acc[4][2];
#pragma unroll
    for (int i = 0; i < 4; i++)
#pragma unroll
        for (int j = 0; j < 2; j++) wmma::fill_fragment(acc[i][j], 0.0f);

    const int iters = Kdim / BK;

    auto load_stage = [&](int s, int k0) {
        float* as = smem + s * STAGE;
        float* bs = as + ASZ;
#pragma unroll
        for (int i = 0; i < 8; i++) {
            int e = i * 128 + tid;
            int r = e >> 3, c = (e & 7) << 2;
            cp16(&as[r * ALD + c], &A[(size_t)(m0 + r) * lda + k0 + c]);
        }
#pragma unroll
        for (int i = 0; i < 4; i++) {
            int e = i * 128 + tid;
            int r = e >> 3, c = (e & 7) << 2;
            cp16(&bs[r * ALD + c], &Bm[(size_t)(n0 + r) * ldb + k0 + c]);
        }
    };

    load_stage(0, 0);
    cp_commit();

    for (int it = 0; it < iters; it++) {
        if (it + 1 < iters) load_stage((it + 1) & 1, (it + 1) * BK);
        cp_commit();              // empty group on last iter keeps counts aligned
        cp_wait<1>();
        __syncthreads();

        const float* as = smem + (it & 1) * STAGE;
        const float* bs = as + ASZ;

#pragma unroll
        for (int kk = 0; kk < BK / 8; kk++) {
            wmma::fragment<wmma::matrix_a, 16, 16, 8, wmma::precision::tf32, wmma::row_major> af[4];
            wmma::fragment<wmma::matrix_b, 16, 16, 8, wmma::precision::tf32, wmma::col_major> bf[2];
#pragma unroll
            for (int i = 0; i < 4; i++)
                wmma::load_matrix_sync(af[i], &as[(wm * 64 + i * 16) * ALD + kk * 8], ALD);
#pragma unroll
            for (int j = 0; j < 2; j++)
                wmma::load_matrix_sync(bf[j], &bs[(wn * 32 + j * 16) * ALD + kk * 8], ALD);
#pragma unroll
            for (int i = 0; i < 4; i++)
#pragma unroll
                for (int j = 0; j < 2; j++)
                    wmma::mma_sync(acc[i][j], af[i], bf[j], acc[i][j]);
        }
        __syncthreads();
    }

    // epilogue through smem (reuse pipeline buffers), float4 global I/O
    constexpr int SLD = BN + 4;   // 68
    float* St = smem;
#pragma unroll
    for (int i = 0; i < 4; i++)
#pragma unroll
        for (int j = 0; j < 2; j++)
            wmma::store_matrix_sync(&St[(wm * 64 + i * 16) * SLD + wn * 32 + j * 16],
                                    acc[i][j], SLD, wmma::mem_row_major);
    __syncthreads();
#pragma unroll
    for (int it = 0; it < 16; it++) {
        int e = it * 128 + tid;
        int r = e >> 4, c = (e & 15) << 2;
        float4 v = *(const float4*)&St[r * SLD + c];
        int row = m0 + r, col = n0 + c;
        size_t ix = (size_t)row * ldc + col;
        if (EPI == 1) {
            v.x += bias[col]; v.y += bias[col + 1]; v.z += bias[col + 2]; v.w += bias[col + 3];
            *(float4*)&C[ix] = v;
        } else if (EPI == 2) {
            float4 o = *(const float4*)&C[ix];
            v.x += o.x; v.y += o.y; v.z += o.z; v.w += o.w;
            *(float4*)&C[ix] = v;
        } else if (EPI == 3) {
            float g = gate[row * NTASK + gcol];
            float4 rs = *(const float4*)&resid[ix];
            v.x = rs.x + g * v.x; v.y = rs.y + g * v.y;
            v.z = rs.z + g * v.z; v.w = rs.w + g * v.w;
            *(float4*)&C[ix] = v;
            float4 t;
            t.x = wmma::__float_to_tf32(v.x); t.y = wmma::__float_to_tf32(v.y);
            t.z = wmma::__float_to_tf32(v.z); t.w = wmma::__float_to_tf32(v.w);
            *(float4*)&Cr[ix] = t;
        } else {
            *(float4*)&C[ix] = v;
        }
    }
}

// ---------------- prep: tf32 splits (+ task transpose) ----------------
// blocks [0,8192): task_mats transpose -> Thi (tf32, 1-term chain)
// [8192,10240): features -> fhi/flo ; [10240,10304): W1 -> W1hi/lo ; [10304,10560): projW -> Phi/Plo
__global__ void __launch_bounds__(256) prep_kernel(
    const float* __restrict__ F, const float* __restrict__ T,
    const float* __restrict__ W1, const float* __restrict__ P)
{
    int b = blockIdx.x, tid = threadIdx.x;
    if (b < 8192) {
        __shared__ float s[32][33];
        int j = b >> 10, t = b & 1023;
        int tr = t >> 5, tc = t & 31;            // k-tile, n-tile
        int x = tid & 31, y = tid >> 5;          // 32 x 8
        const float* src = T + (size_t)j * FDIM * FDIM;
#pragma unroll
        for (int i = 0; i < 4; i++)
            s[y + i * 8][x] = src[(size_t)(tr * 32 + y + i * 8) * FDIM + tc * 32 + x];
        __syncthreads();
        float* dh = g_Thi + (size_t)j * FDIM * FDIM;
#pragma unroll
        for (int i = 0; i < 4; i++) {
            int n = tc * 32 + y + i * 8, k = tr * 32 + x;
            dh[(size_t)n * FDIM + k] = wmma::__float_to_tf32(s[x][y + i * 8]);
        }
    } else if (b < 10240) {
        size_t base = (size_t)(b - 8192) * 4096 + tid * 16;
#pragma unroll
        for (int q = 0; q < 4; q++) {
            float4 v = *(const float4*)&F[base + q * 4];
            float vv[4] = {v.x, v.y, v.z, v.w};
#pragma unroll
            for (int e = 0; e < 4; e++) {
                size_t ix = base + q * 4 + e;
                float hi = wmma::__float_to_tf32(vv[e]);
                g_fhi[ix] = hi;
                g_flo[ix] = wmma::__float_to_tf32(vv[e] - hi);
            }
        }
    } else if (b < 10304) {
        size_t base = (size_t)(b - 10240) * 4096 + tid * 16;
#pragma unroll
        for (int q = 0; q < 4; q++) {
            float4 v = *(const float4*)&W1[base + q * 4];
            float vv[4] = {v.x, v.y, v.z, v.w};
#pragma unroll
            for (int e = 0; e < 4; e++) {
                size_t ix = base + q * 4 + e;
                float hi = wmma::__float_to_tf32(vv[e]);
                g_W1hi[ix] = hi;
                g_W1lo[ix] = wmma::__float_to_tf32(vv[e] - hi);
            }
        }
    } else {
        size_t base = (size_t)(b - 10304) * 4096 + tid * 16;
#pragma unroll
        for (int q = 0; q < 4; q++) {
            float4 v = *(const float4*)&P[base + q * 4];
            float vv[4] = {v.x, v.y, v.z, v.w};
#pragma unroll
            for (int e = 0; e < 4; e++) {
                size_t ix = base + q * 4 + e;
                float hi = wmma::__float_to_tf32(vv[e]);
                g_Phi[ix] = hi;
                g_Plo[ix] = wmma::__float_to_tf32(vv[e] - hi);
            }
        }
    }
}

// ---------------- split x (chain output) into tf32 hi/lo for proj ----------------
__global__ void __launch_bounds__(256) splitx_kernel(const float* __restrict__ X)
{
    size_t base = (size_t)blockIdx.x * 4096 + threadIdx.x * 16;
#pragma unroll
    for (int q = 0; q < 4; q++) {
        float4 v = *(const float4*)&X[base + q * 4];
        float vv[4] = {v.x, v.y, v.z, v.w};
#pragma unroll
        for (int e = 0; e < 4; e++) {
            size_t ix = base + q * 4 + e;
            float hi = wmma::__float_to_tf32(vv[e]);
            g_fhi[ix] = hi;                                   // reuse feature split buffers
            g_flo[ix] = wmma::__float_to_tf32(vv[e] - hi);
        }
    }
}

// ---------------- coeffs = relu(h) @ W2^T + b2 (proven) ----------------
__global__ void coeffs_kernel(const float* __restrict__ W2, const float* __restrict__ b2)
{
    int tid = threadIdx.x;
    int row = blockIdx.x * 32 + (tid >> 3);
    int k = tid & 7;
    const float* hr = g_h + (size_t)row * HDIM;
    const float* w = W2 + k * HDIM;
    float s = b2[k];
#pragma unroll 8
    for (int h = 0; h < HDIM; h++) s += fmaxf(hr[h], 0.0f) * w[h];
    g_coeffs[row * NTASK + k] = s;
}

// ---------------- unc^2[b,k] = a^T G a (proven) ----------------
__global__ void __launch_bounds__(256) unc_kernel(const float* __restrict__ W2)
{
    __shared__ float W2s[NTASK * HDIM];
    __shared__ float Gs[HDIM * 32];
    int tid = threadIdx.x, lane = tid & 31, warp = tid >> 5;
    for (int i = tid; i < NTASK * HDIM; i += 256) W2s[i] = W2[i];

    int row = blockIdx.x * 8 + warp;
    const float* hr = g_h + (size_t)row * HDIM;
    unsigned mb[8];
#pragma unroll
    for (int j = 0; j < 8; j++)
        mb[j] = __ballot_sync(0xffffffffu, hr[j * 32 + lane] > 0.0f);

    float u2[8];
#pragma unroll
    for (int k = 0; k < 8; k++) u2[k] = 0.0f;

    for (int c = 0; c < 8; c++) {
        __syncthreads();
        for (int i = tid; i < HDIM * 32; i += 256) {
            int h = i >> 5, l = i & 31;
            Gs[i] = g_G[h * HDIM + c * 32 + l];
        }
        __syncthreads();
        float t[8];
#pragma unroll
        for (int k = 0; k < 8; k++) t[k] = 0.0f;
        for (int h = 0; h < HDIM; h++) {
            if ((mb[h >> 5] >> (h & 31)) & 1u) {     // warp-uniform branch
                float gv = Gs[h * 32 + lane];
#pragma unroll
                for (int k = 0; k < 8; k++) t[k] += W2s[k * HDIM + h] * gv;
            }
        }
        int hp = c * 32 + lane;
        if ((mb[hp >> 5] >> (hp & 31)) & 1u) {
#pragma unroll
            for (int k = 0; k < 8; k++) u2[k] += W2s[k * HDIM + hp] * t[k];
        }
    }
#pragma unroll
    for (int k = 0; k < 8; k++) {
        float v = u2[k];
        for (int off = 16; off; off >>= 1) v += __shfl_down_sync(0xffffffffu, v, off);
        if (lane == 0) {
            v = fmaxf(v, 0.0f);
            g_unc2[row * NTASK + k] = v;
            atomicMax(&g_max2bits, __float_as_uint(v));
        }
    }
}

// ---------------- gating (proven) ----------------
__global__ void gate_kernel(const float* __restrict__ bthr, const float* __restrict__ beta)
{
    int i = blockIdx.x * blockDim.x + threadIdx.x;
    if (i >= BATCH * NTASK) return;
    float max2 = __uint_as_float(g_max2bits);
    float u = (max2 > 0.0f) ? sqrtf(g_unc2[i] / max2) : sqrtf(g_unc2[i]);
    float base = log1pf(expf(bthr[0]));          // softplus
    float thr = base * (1.0f + fmaxf(beta[0], 0.0f) * u);
    float cf = g_coeffs[i];
    g_gated[i] = (fabsf(cf) < thr) ? 0.0f : cf;
}

// ---------------- launch ----------------
extern "C" void kernel_launch(void* const* d_in, const int* in_sizes, int n_in,
                              void* d_out, int out_size)
{
    const float* features = (const float*)d_in[0];
    const float* W1   = (const float*)d_in[1];
    const float* b1   = (const float*)d_in[2];
    const float* W2   = (const float*)d_in[3];
    const float* b2   = (const float*)d_in[4];
    const float* task = (const float*)d_in[5];
    const float* projW = (const float*)d_in[6];
    const float* bthr = (const float*)d_in[7];
    const float* beta = (const float*)d_in[8];
    float* out = (float*)d_out;

    float *fhi, *flo, *w1hi, *w1lo, *thi, *phi, *plo;
    float *xa, *xar, *xb, *xbr, *hbuf, *Gbuf, *gated;
    void* maxp;
    cudaGetSymbolAddress((void**)&fhi, g_fhi);   cudaGetSymbolAddress((void**)&flo, g_flo);
    cudaGetSymbolAddress((void**)&w1hi, g_W1hi); cudaGetSymbolAddress((void**)&w1lo, g_W1lo);
    cudaGetSymbolAddress((void**)&thi, g_Thi);
    cudaGetSymbolAddress((void**)&phi, g_Phi);   cudaGetSymbolAddress((void**)&plo, g_Plo);
    cudaGetSymbolAddress((void**)&xa, g_xa);     cudaGetSymbolAddress((void**)&xar, g_xar);
    cudaGetSymbolAddress((void**)&xb, g_xb);     cudaGetSymbolAddress((void**)&xbr, g_xbr);
    cudaGetSymbolAddress((void**)&hbuf, g_h);    cudaGetSymbolAddress((void**)&Gbuf, g_G);
    cudaGetSymbolAddress((void**)&gated, g_gated);
    cudaGetSymbolAddress(&maxp, g_max2bits);

    const int smem = 2 * STAGE * 4;   // 55296 B
    cudaFuncSetAttribute(gemm_tf32<0>, cudaFuncAttributeMaxDynamicSharedMemorySize, smem);
    cudaFuncSetAttribute(gemm_tf32<1>, cudaFuncAttributeMaxDynamicSharedMemorySize, smem);
    cudaFuncSetAttribute(gemm_tf32<2>, cudaFuncAttributeMaxDynamicSharedMemorySize, smem);
    cudaFuncSetAttribute(gemm_tf32<3>, cudaFuncAttributeMaxDynamicSharedMemorySize, smem);

    cudaMemsetAsync(maxp, 0, 4);

    // (1) prep
    prep_kernel<<<10560, 256>>>(features, task, W1, projW);

    dim3 gG(HDIM / BN, HDIM / BM);       // 4 x 2
    dim3 gH(HDIM / BN, BATCH / BM);      // 4 x 64
    dim3 gX(FDIM / BN, BATCH / BM);      // 16 x 64

    // (2-4) G = W1 @ W1^T  (3xTF32 via 3 launches)
    gemm_tf32<0><<<gG, 128, smem>>>(w1hi, FDIM, w1hi, FDIM, Gbuf, HDIM, FDIM, nullptr, nullptr, nullptr, 0, nullptr);
    gemm_tf32<2><<<gG, 128, smem>>>(w1hi, FDIM, w1lo, FDIM, Gbuf, HDIM, FDIM, nullptr, nullptr, nullptr, 0, nullptr);
    gemm_tf32<2><<<gG, 128, smem>>>(w1lo, FDIM, w1hi, FDIM, Gbuf, HDIM, FDIM, nullptr, nullptr, nullptr, 0, nullptr);

    // (5-7) h = F @ W1^T + b1  (3xTF32 via 3 launches; slot 5 of ncu lands here)
    gemm_tf32<1><<<gH, 128, smem>>>(fhi, FDIM, w1hi, FDIM, hbuf, HDIM, FDIM, b1, nullptr, nullptr, 0, nullptr);
    gemm_tf32<2><<<gH, 128, smem>>>(fhi, FDIM, w1lo, FDIM, hbuf, HDIM, FDIM, nullptr, nullptr, nullptr, 0, nullptr);
    gemm_tf32<2><<<gH, 128, smem>>>(flo, FDIM, w1hi, FDIM, hbuf, HDIM, FDIM, nullptr, nullptr, nullptr, 0, nullptr);

    // (8-10) coeffs, unc, gate
    coeffs_kernel<<<BATCH / 32, 256>>>(W2, b2);
    unc_kernel<<<BATCH / 8, 256>>>(W2);
    gate_kernel<<<(BATCH * NTASK + 255) / 256, 256>>>(bthr, beta);

    // (11-18) chain: x <- x + g_j * (x @ T_j)   (1xTF32; A = RN-rounded copy)
    const float* rin = features;  const float* ain = fhi;
    float* outf = xa;             float* outr = xar;
    for (int j = 0; j < NTASK; j++) {
        gemm_tf32<3><<<gX, 128, smem>>>(
            ain, FDIM, thi + (size_t)j * FDIM * FDIM, FDIM,
            outf, FDIM, FDIM, nullptr, rin, gated, j, outr);
        rin = outf; ain = outr;
        if (outf == xa) { outf = xb; outr = xbr; }
        else            { outf = xa; outr = xar; }
    }

    // (19) split final x into tf32 hi/lo (reuses fhi/flo)
    splitx_kernel<<<BATCH * FDIM / 4096, 256>>>(rin);

    // (20-22) out = x @ proj_W^T  (3xTF32 via 3 launches)
    gemm_tf32<0><<<gX, 128, smem>>>(fhi, FDIM, phi, FDIM, out, FDIM, FDIM, nullptr, nullptr, nullptr, 0, nullptr);
    gemm_tf32<2><<<gX, 128, smem>>>(fhi, FDIM, plo, FDIM, out, FDIM, FDIM, nullptr, nullptr, nullptr, 0, nullptr);
    gemm_tf32<2><<<gX, 128, smem>>>(flo, FDIM, phi, FDIM, out, FDIM, FDIM, nullptr, nullptr, nullptr, 0, nullptr);
}

// round 6
// speedup vs baseline: 2.5703x; 2.4112x over previous
#include <cuda_runtime.h>
#include <mma.h>
#include <cstdint>
#include <cstddef>

using namespace nvcuda;

#define BATCH 8192
#define FDIM  1024
#define HDIM  256
#define NTASK 8

// ---------------- scratch (static device globals; no allocation) ----------------
__device__ float g_fhi[BATCH * FDIM], g_flo[BATCH * FDIM];   // features tf32 split; reused for final-x split
__device__ float g_W1hi[HDIM * FDIM], g_W1lo[HDIM * FDIM];
__device__ float g_Thi[NTASK * FDIM * FDIM];                 // task mats transposed to [N,K], tf32
__device__ float g_Phi[FDIM * FDIM], g_Plo[FDIM * FDIM];     // projW split ([N,K] layout already)
__device__ float g_xa[BATCH * FDIM], g_xar[BATCH * FDIM];    // chain ping-pong (full + tf32-rounded)
__device__ float g_xb[BATCH * FDIM], g_xbr[BATCH * FDIM];
__device__ float    g_h[BATCH * HDIM];
__device__ float    g_G[HDIM * HDIM];
__device__ float    g_coeffs[BATCH * NTASK];
__device__ float    g_unc2[BATCH * NTASK];
__device__ unsigned g_max2bits;
__device__ float    g_gated[BATCH * NTASK];
__device__ int      g_cnt[NTASK];
__device__ int      g_idx[NTASK * BATCH];
__device__ unsigned g_notident;

// ---------------- cp.async helpers ----------------
__device__ __forceinline__ void cp16(float* s, const float* g) {
    unsigned sa = (unsigned)__cvta_generic_to_shared(s);
    asm volatile("cp.async.cg.shared.global [%0], [%1], 16;" :: "r"(sa), "l"(g));
}
__device__ __forceinline__ void cp_commit() { asm volatile("cp.async.commit_group;"); }
template <int N> __device__ __forceinline__ void cp_wait() {
    asm volatile("cp.async.wait_group %0;" :: "n"(N));
}

// ---------------- tf32 GEMM: C[M,N] = A[M,K] @ B[N,K]^T ----------------
// Operands PRE-ROUNDED to tf32 values -> no cvt in inner loop.
// THREE: in-kernel 3-term (A_hi B_hi + A_hi B_lo + A_lo B_hi).
// EPI: 0 = store, 1 = +bias store, 3 = chain (resid + gate*acc -> C, tf32 -> Cr),
//      5 = proj (if g_notident==0: C = resid copy, skip GEMM).
// GATHER: A rows / C rows indirected through idx[0..*cnt).
constexpr int BM = 128, BN = 64, BK = 32;
constexpr int ALD = BK + 4;                 // 36
constexpr int ASZ = BM * ALD;               // 4608
constexpr int BSZ = BN * ALD;               // 2304

template <bool THREE, int EPI, bool GATHER>
__global__ void __launch_bounds__(128) gemm_tf32(
    const float* __restrict__ A, const float* __restrict__ Alo, int lda,
    const float* __restrict__ Bm, const float* __restrict__ Blo, int ldb,
    float* __restrict__ C, int ldc, int Kdim,
    const float* __restrict__ bias,
    const float* __restrict__ resid,
    const float* __restrict__ gate, int gcol,
    float* __restrict__ Cr,
    const int* __restrict__ idx, const int* __restrict__ cnt)
{
    constexpr int NTA = THREE ? 2 : 1;                   // A tiles per stage
    constexpr int STAGE = NTA * ASZ + NTA * BSZ;

    extern __shared__ float smem[];
    __shared__ int sidx[BM];

    const int tid = threadIdx.x;
    const int m0 = blockIdx.y * BM;
    const int n0 = blockIdx.x * BN;
    const int warp = tid >> 5;
    const int wm = warp >> 1;
    const int wn = warp & 1;

    if (EPI == 5) {
        // proj with identity fast path
        if (g_notident == 0u) {
#pragma unroll
            for (int it = 0; it < 16; it++) {
                int e = it * 128 + tid;
                int r = e >> 4, c = (e & 15) << 2;
                size_t ix = (size_t)(m0 + r) * ldc + n0 + c;
                *(float4*)&C[ix] = *(const float4*)&resid[ix];
            }
            return;
        }
    }

    int n_act = 0;
    if (GATHER) {
        n_act = *cnt;
        if (m0 >= n_act) return;
        int m = m0 + tid;
        if (tid < BM) sidx[tid] = (m < n_act) ? idx[m] : idx[m0];
        __syncthreads();
    }

    wmma::fragment<wmma::accumulator, 16, 16, 8, float> acc[4][2];
#pragma unroll
    for (int i = 0; i < 4; i++)
#pragma unroll
        for (int j = 0; j < 2; j++) wmma::fill_fragment(acc[i][j], 0.0f);

    const int iters = Kdim / BK;

    auto load_stage = [&](int s, int k0) {
        float* as = smem + s * STAGE;
        float* al = as + ASZ;                        // valid when THREE
        float* bs = as + NTA * ASZ;
        float* bl = bs + BSZ;
#pragma unroll
        for (int i = 0; i < 8; i++) {
            int e = i * 128 + tid;
            int r = e >> 3, c = (e & 7) << 2;
            int grow = GATHER ? sidx[r] : (m0 + r);
            cp16(&as[r * ALD + c], &A[(size_t)grow * lda + k0 + c]);
            if (THREE) cp16(&al[r * ALD + c], &Alo[(size_t)grow * lda + k0 + c]);
        }
#pragma unroll
        for (int i = 0; i < 4; i++) {
            int e = i * 128 + tid;
            int r = e >> 3, c = (e & 7) << 2;
            cp16(&bs[r * ALD + c], &Bm[(size_t)(n0 + r) * ldb + k0 + c]);
            if (THREE) cp16(&bl[r * ALD + c], &Blo[(size_t)(n0 + r) * ldb + k0 + c]);
        }
    };

    load_stage(0, 0);
    cp_commit();

    for (int it = 0; it < iters; it++) {
        if (it + 1 < iters) load_stage((it + 1) & 1, (it + 1) * BK);
        cp_commit();              // empty group on last iter keeps counts aligned
        cp_wait<1>();
        __syncthreads();

        const float* as = smem + (it & 1) * STAGE;
        const float* al = as + ASZ;
        const float* bs = as + NTA * ASZ;
        const float* bl = bs + BSZ;

#pragma unroll
        for (int kk = 0; kk < BK / 8; kk++) {
            wmma::fragment<wmma::matrix_a, 16, 16, 8, wmma::precision::tf32, wmma::row_major> af[4], afl[THREE ? 4 : 1];
            wmma::fragment<wmma::matrix_b, 16, 16, 8, wmma::precision::tf32, wmma::col_major> bf[2], bfl[THREE ? 2 : 1];
#pragma unroll
            for (int i = 0; i < 4; i++) {
                wmma::load_matrix_sync(af[i], &as[(wm * 64 + i * 16) * ALD + kk * 8], ALD);
                if (THREE)
                    wmma::load_matrix_sync(afl[i], &al[(wm * 64 + i * 16) * ALD + kk * 8], ALD);
            }
#pragma unroll
            for (int j = 0; j < 2; j++) {
                wmma::load_matrix_sync(bf[j], &bs[(wn * 32 + j * 16) * ALD + kk * 8], ALD);
                if (THREE)
                    wmma::load_matrix_sync(bfl[j], &bl[(wn * 32 + j * 16) * ALD + kk * 8], ALD);
            }
#pragma unroll
            for (int i = 0; i < 4; i++)
#pragma unroll
                for (int j = 0; j < 2; j++) {
                    if (THREE) {
                        wmma::mma_sync(acc[i][j], af[i], bfl[j], acc[i][j]);
                        wmma::mma_sync(acc[i][j], afl[i], bf[j], acc[i][j]);
                    }
                    wmma::mma_sync(acc[i][j], af[i], bf[j], acc[i][j]);
                }
        }
        __syncthreads();
    }

    // epilogue through smem, float4 global I/O
    constexpr int SLD = BN + 4;   // 68
    float* St = smem;
#pragma unroll
    for (int i = 0; i < 4; i++)
#pragma unroll
        for (int j = 0; j < 2; j++)
            wmma::store_matrix_sync(&St[(wm * 64 + i * 16) * SLD + wn * 32 + j * 16],
                                    acc[i][j], SLD, wmma::mem_row_major);
    __syncthreads();
#pragma unroll
    for (int it = 0; it < 16; it++) {
        int e = it * 128 + tid;
        int r = e >> 4, c = (e & 15) << 2;
        float4 v = *(const float4*)&St[r * SLD + c];
        int col = n0 + c;
        if (EPI == 3) {
            if (m0 + r >= n_act) continue;
            int grow = sidx[r];
            size_t ix = (size_t)grow * ldc + col;
            float g = gate[grow * NTASK + gcol];
            float4 rs = *(const float4*)&resid[ix];
            v.x = rs.x + g * v.x; v.y = rs.y + g * v.y;
            v.z = rs.z + g * v.z; v.w = rs.w + g * v.w;
            *(float4*)&C[ix] = v;
            float4 t;
            t.x = wmma::__float_to_tf32(v.x); t.y = wmma::__float_to_tf32(v.y);
            t.z = wmma::__float_to_tf32(v.z); t.w = wmma::__float_to_tf32(v.w);
            *(float4*)&Cr[ix] = t;
        } else {
            size_t ix = (size_t)(m0 + r) * ldc + col;
            if (EPI == 1) {
                v.x += bias[col]; v.y += bias[col + 1];
                v.z += bias[col + 2]; v.w += bias[col + 3];
            }
            *(float4*)&C[ix] = v;
        }
    }
}

// ---------------- prep: tf32 splits (+ task transpose) ----------------
__global__ void __launch_bounds__(256) prep_kernel(
    const float* __restrict__ F, const float* __restrict__ T,
    const float* __restrict__ W1, const float* __restrict__ P)
{
    int b = blockIdx.x, tid = threadIdx.x;
    if (b < 8192) {
        __shared__ float s[32][33];
        int j = b >> 10, t = b & 1023;
        int tr = t >> 5, tc = t & 31;
        int x = tid & 31, y = tid >> 5;
        const float* src = T + (size_t)j * FDIM * FDIM;
#pragma unroll
        for (int i = 0; i < 4; i++)
            s[y + i * 8][x] = src[(size_t)(tr * 32 + y + i * 8) * FDIM + tc * 32 + x];
        __syncthreads();
        float* dh = g_Thi + (size_t)j * FDIM * FDIM;
#pragma unroll
        for (int i = 0; i < 4; i++) {
            int n = tc * 32 + y + i * 8, k = tr * 32 + x;
            dh[(size_t)n * FDIM + k] = wmma::__float_to_tf32(s[x][y + i * 8]);
        }
    } else if (b < 10240) {
        size_t base = (size_t)(b - 8192) * 4096 + tid * 16;
#pragma unroll
        for (int q = 0; q < 4; q++) {
            float4 v = *(const float4*)&F[base + q * 4];
            float vv[4] = {v.x, v.y, v.z, v.w};
#pragma unroll
            for (int e = 0; e < 4; e++) {
                size_t ix = base + q * 4 + e;
                float hi = wmma::__float_to_tf32(vv[e]);
                g_fhi[ix] = hi;
                g_flo[ix] = wmma::__float_to_tf32(vv[e] - hi);
            }
        }
    } else if (b < 10304) {
        size_t base = (size_t)(b - 10240) * 4096 + tid * 16;
#pragma unroll
        for (int q = 0; q < 4; q++) {
            float4 v = *(const float4*)&W1[base + q * 4];
            float vv[4] = {v.x, v.y, v.z, v.w};
#pragma unroll
            for (int e = 0; e < 4; e++) {
                size_t ix = base + q * 4 + e;
                float hi = wmma::__float_to_tf32(vv[e]);
                g_W1hi[ix] = hi;
                g_W1lo[ix] = wmma::__float_to_tf32(vv[e] - hi);
            }
        }
    } else {
        size_t base = (size_t)(b - 10304) * 4096 + tid * 16;
#pragma unroll
        for (int q = 0; q < 4; q++) {
            float4 v = *(const float4*)&P[base + q * 4];
            float vv[4] = {v.x, v.y, v.z, v.w};
#pragma unroll
            for (int e = 0; e < 4; e++) {
                size_t ix = base + q * 4 + e;
                float hi = wmma::__float_to_tf32(vv[e]);
                g_Phi[ix] = hi;
                g_Plo[ix] = wmma::__float_to_tf32(vv[e] - hi);
            }
        }
    }
}

// ---------------- proj identity check ----------------
__global__ void projchk_kernel(const float* __restrict__ P)
{
    int e = blockIdx.x * 256 + threadIdx.x;      // one float4 per thread
    int idx4 = e * 4;
    int row = idx4 >> 10;
    float4 v = *(const float4*)&P[idx4];
    float vv[4] = {v.x, v.y, v.z, v.w};
    bool bad = false;
#pragma unroll
    for (int q = 0; q < 4; q++) {
        int col = (idx4 + q) & 1023;
        float exp = (col == row) ? 1.0f : 0.0f;
        if (vv[q] != exp) bad = true;
    }
    if (__syncthreads_or(bad) && threadIdx.x == 0) atomicOr(&g_notident, 1u);
}

// ---------------- split final x into tf32 hi/lo (only needed if proj != I) ----------------
__global__ void __launch_bounds__(256) splitx_kernel(const float* __restrict__ X)
{
    if (g_notident == 0u) return;
    size_t base = (size_t)blockIdx.x * 4096 + threadIdx.x * 16;
#pragma unroll
    for (int q = 0; q < 4; q++) {
        float4 v = *(const float4*)&X[base + q * 4];
        float vv[4] = {v.x, v.y, v.z, v.w};
#pragma unroll
        for (int e = 0; e < 4; e++) {
            size_t ix = base + q * 4 + e;
            float hi = wmma::__float_to_tf32(vv[e]);
            g_fhi[ix] = hi;
            g_flo[ix] = wmma::__float_to_tf32(vv[e] - hi);
        }
    }
}

// ---------------- coeffs = relu(h) @ W2^T + b2 ----------------
__global__ void coeffs_kernel(const float* __restrict__ W2, const float* __restrict__ b2)
{
    int tid = threadIdx.x;
    int row = blockIdx.x * 32 + (tid >> 3);
    int k = tid & 7;
    const float* hr = g_h + (size_t)row * HDIM;
    const float* w = W2 + k * HDIM;
    float s = b2[k];
#pragma unroll 8
    for (int h = 0; h < HDIM; h++) s += fmaxf(hr[h], 0.0f) * w[h];
    g_coeffs[row * NTASK + k] = s;
}

// ---------------- unc^2[b,k] = a^T G a ----------------
__global__ void __launch_bounds__(256) unc_kernel(const float* __restrict__ W2)
{
    __shared__ float W2s[NTASK * HDIM];
    __shared__ float Gs[HDIM * 32];
    int tid = threadIdx.x, lane = tid & 31, warp = tid >> 5;
    for (int i = tid; i < NTASK * HDIM; i += 256) W2s[i] = W2[i];

    int row = blockIdx.x * 8 + warp;
    const float* hr = g_h + (size_t)row * HDIM;
    unsigned mb[8];
#pragma unroll
    for (int j = 0; j < 8; j++)
        mb[j] = __ballot_sync(0xffffffffu, hr[j * 32 + lane] > 0.0f);

    float u2[8];
#pragma unroll
    for (int k = 0; k < 8; k++) u2[k] = 0.0f;

    for (int c = 0; c < 8; c++) {
        __syncthreads();
        for (int i = tid; i < HDIM * 32; i += 256) {
            int h = i >> 5, l = i & 31;
            Gs[i] = g_G[h * HDIM + c * 32 + l];
        }
        __syncthreads();
        float t[8];
#pragma unroll
        for (int k = 0; k < 8; k++) t[k] = 0.0f;
        for (int h = 0; h < HDIM; h++) {
            if ((mb[h >> 5] >> (h & 31)) & 1u) {
                float gv = Gs[h * 32 + lane];
#pragma unroll
                for (int k = 0; k < 8; k++) t[k] += W2s[k * HDIM + h] * gv;
            }
        }
        int hp = c * 32 + lane;
        if ((mb[hp >> 5] >> (hp & 31)) & 1u) {
#pragma unroll
            for (int k = 0; k < 8; k++) u2[k] += W2s[k * HDIM + hp] * t[k];
        }
    }
#pragma unroll
    for (int k = 0; k < 8; k++) {
        float v = u2[k];
        for (int off = 16; off; off >>= 1) v += __shfl_down_sync(0xffffffffu, v, off);
        if (lane == 0) {
            v = fmaxf(v, 0.0f);
            g_unc2[row * NTASK + k] = v;
            atomicMax(&g_max2bits, __float_as_uint(v));
        }
    }
}

// ---------------- gating + active-row compaction ----------------
__global__ void gate_kernel(const float* __restrict__ bthr, const float* __restrict__ beta)
{
    int i = blockIdx.x * blockDim.x + threadIdx.x;
    if (i >= BATCH * NTASK) return;
    int row = i >> 3, k = i & 7;
    float max2 = __uint_as_float(g_max2bits);
    float u = (max2 > 0.0f) ? sqrtf(g_unc2[i] / max2) : sqrtf(g_unc2[i]);
    float base = log1pf(expf(bthr[0]));
    float thr = base * (1.0f + fmaxf(beta[0], 0.0f) * u);
    float cf = g_coeffs[i];
    float gf = (fabsf(cf) < thr) ? 0.0f : cf;
    g_gated[i] = gf;
    if (gf != 0.0f) {
        int p = atomicAdd(&g_cnt[k], 1);
        g_idx[k * BATCH + p] = row;
    }
}

// ---------------- copy rows with zero gate (chain step j) ----------------
__global__ void __launch_bounds__(256) copy_inactive(
    const float* __restrict__ xin, const float* __restrict__ xinr,
    float* __restrict__ xout, float* __restrict__ xoutr, int j)
{
    int row = blockIdx.x;
    if (g_gated[row * NTASK + j] != 0.0f) return;
    size_t b4 = (size_t)row * (FDIM / 4) + threadIdx.x;
    ((float4*)xout)[b4] = ((const float4*)xin)[b4];
    ((float4*)xoutr)[b4] = ((const float4*)xinr)[b4];
}

// ---------------- launch ----------------
extern "C" void kernel_launch(void* const* d_in, const int* in_sizes, int n_in,
                              void* d_out, int out_size)
{
    const float* features = (const float*)d_in[0];
    const float* W1   = (const float*)d_in[1];
    const float* b1   = (const float*)d_in[2];
    const float* W2   = (const float*)d_in[3];
    const float* b2   = (const float*)d_in[4];
    const float* task = (const float*)d_in[5];
    const float* projW = (const float*)d_in[6];
    const float* bthr = (const float*)d_in[7];
    const float* beta = (const float*)d_in[8];
    float* out = (float*)d_out;

    float *fhi, *flo, *w1hi, *w1lo, *thi, *phi, *plo;
    float *xa, *xar, *xb, *xbr, *hbuf, *Gbuf, *gated;
    int *idxp, *cntp;
    void *maxp, *nip;
    cudaGetSymbolAddress((void**)&fhi, g_fhi);   cudaGetSymbolAddress((void**)&flo, g_flo);
    cudaGetSymbolAddress((void**)&w1hi, g_W1hi); cudaGetSymbolAddress((void**)&w1lo, g_W1lo);
    cudaGetSymbolAddress((void**)&thi, g_Thi);
    cudaGetSymbolAddress((void**)&phi, g_Phi);   cudaGetSymbolAddress((void**)&plo, g_Plo);
    cudaGetSymbolAddress((void**)&xa, g_xa);     cudaGetSymbolAddress((void**)&xar, g_xar);
    cudaGetSymbolAddress((void**)&xb, g_xb);     cudaGetSymbolAddress((void**)&xbr, g_xbr);
    cudaGetSymbolAddress((void**)&hbuf, g_h);    cudaGetSymbolAddress((void**)&Gbuf, g_G);
    cudaGetSymbolAddress((void**)&gated, g_gated);
    cudaGetSymbolAddress((void**)&idxp, g_idx);  cudaGetSymbolAddress((void**)&cntp, g_cnt);
    cudaGetSymbolAddress(&maxp, g_max2bits);     cudaGetSymbolAddress(&nip, g_notident);

    const int smem1 = 2 * (ASZ + BSZ) * 4;           // 55296
    const int smem3 = 2 * 2 * (ASZ + BSZ) * 4;       // 110592
    cudaFuncSetAttribute(gemm_tf32<true,  0, false>, cudaFuncAttributeMaxDynamicSharedMemorySize, smem3);
    cudaFuncSetAttribute(gemm_tf32<true,  1, false>, cudaFuncAttributeMaxDynamicSharedMemorySize, smem3);
    cudaFuncSetAttribute(gemm_tf32<true,  5, false>, cudaFuncAttributeMaxDynamicSharedMemorySize, smem3);
    cudaFuncSetAttribute(gemm_tf32<false, 3, true >, cudaFuncAttributeMaxDynamicSharedMemorySize, smem1);

    cudaMemsetAsync(maxp, 0, 4);
    cudaMemsetAsync(cntp, 0, NTASK * sizeof(int));
    cudaMemsetAsync(nip, 0, 4);

    // (1) prep + proj identity check
    prep_kernel<<<10560, 256>>>(features, task, W1, projW);
    projchk_kernel<<<1024, 256>>>(projW);

    dim3 gG(HDIM / BN, HDIM / BM);       // 4 x 2
    dim3 gH(HDIM / BN, BATCH / BM);      // 4 x 64
    dim3 gX(FDIM / BN, BATCH / BM);      // 16 x 64

    // (2) h = F @ W1^T + b1  (in-kernel 3-term tf32)
    gemm_tf32<true, 1, false><<<gH, 128, smem3>>>(
        fhi, flo, FDIM, w1hi, w1lo, FDIM, hbuf, HDIM, FDIM,
        b1, nullptr, nullptr, 0, nullptr, nullptr, nullptr);

    // (3) G = W1 @ W1^T  (in-kernel 3-term)
    gemm_tf32<true, 0, false><<<gG, 128, smem3>>>(
        w1hi, w1lo, FDIM, w1hi, w1lo, FDIM, Gbuf, HDIM, FDIM,
        nullptr, nullptr, nullptr, 0, nullptr, nullptr, nullptr);

    // (4-6) coeffs, unc, gate+compact
    coeffs_kernel<<<BATCH / 32, 256>>>(W2, b2);
    unc_kernel<<<BATCH / 8, 256>>>(W2);
    gate_kernel<<<(BATCH * NTASK + 255) / 256, 256>>>(bthr, beta);

    // (7..) chain: active rows via gathered GEMM, inactive rows via copy
    const float* rin = features;  const float* ain = fhi;
    float* outf = xa;             float* outr = xar;
    for (int j = 0; j < NTASK; j++) {
        copy_inactive<<<BATCH, 256>>>(rin, ain, outf, outr, j);
        gemm_tf32<false, 3, true><<<gX, 128, smem1>>>(
            ain, nullptr, FDIM, thi + (size_t)j * FDIM * FDIM, nullptr, FDIM,
            outf, FDIM, FDIM, nullptr, rin, gated, j, outr,
            idxp + j * BATCH, cntp + j);
        rin = outf; ain = outr;
        if (outf == xa) { outf = xb; outr = xbr; }
        else            { outf = xa; outr = xar; }
    }

    // final split (no-op when proj == I)
    splitx_kernel<<<BATCH * FDIM / 4096, 256>>>(rin);

    // proj: identity -> copy, else 3-term GEMM
    gemm_tf32<true, 5, false><<<gX, 128, smem3>>>(
        fhi, flo, FDIM, phi, plo, FDIM, out, FDIM, FDIM,
        nullptr, rin, nullptr, 0, nullptr, nullptr, nullptr);
}

// round 7
// speedup vs baseline: 2.8560x; 1.1111x over previous
#include <cuda_runtime.h>
#include <mma.h>
#include <cstdint>
#include <cstddef>

using namespace nvcuda;

#define BATCH 8192
#define FDIM  1024
#define HDIM  256
#define NTASK 8

// ---------------- scratch (static device globals; no allocation) ----------------
__device__ float g_fhi[BATCH * FDIM], g_flo[BATCH * FDIM];   // features tf32 split; reused for final-x split
__device__ float g_W1hi[HDIM * FDIM], g_W1lo[HDIM * FDIM];
__device__ float g_Thi[NTASK * FDIM * FDIM];                 // task mats transposed to [N,K], tf32
__device__ float g_Phi[FDIM * FDIM], g_Plo[FDIM * FDIM];     // projW split ([N,K] layout already)
__device__ float g_xa[BATCH * FDIM];                         // chain x, updated IN PLACE
__device__ float g_xar[BATCH * FDIM], g_xbr[BATCH * FDIM];   // tf32-rounded x ping-pong (A operand)
__device__ float g_hpart[2 * BATCH * HDIM];                  // h split-K partials
__device__ float    g_h[BATCH * HDIM];
__device__ float    g_G[HDIM * HDIM];
__device__ float    g_coeffs[BATCH * NTASK];
__device__ float    g_unc2[BATCH * NTASK];
__device__ unsigned g_max2bits;
__device__ float    g_gated[BATCH * NTASK];
__device__ int      g_cnt[NTASK];
__device__ int      g_idx[NTASK * BATCH];
__device__ unsigned g_notident;

// ---------------- cp.async helpers ----------------
__device__ __forceinline__ void cp16(float* s, const float* g) {
    unsigned sa = (unsigned)__cvta_generic_to_shared(s);
    asm volatile("cp.async.cg.shared.global [%0], [%1], 16;" :: "r"(sa), "l"(g));
}
__device__ __forceinline__ void cp_commit() { asm volatile("cp.async.commit_group;"); }
template <int N> __device__ __forceinline__ void cp_wait() {
    asm volatile("cp.async.wait_group %0;" :: "n"(N));
}

// ---------------- tf32 GEMM: C[M,N] = A[M,K] @ B[N,K]^T ----------------
// 256 threads (8 warps, 32x32 warp tiles), 128x64x32 CTA tile, cp.async double buffer.
// Operands PRE-ROUNDED to tf32 -> no cvt in inner loop.
// THREE: in-kernel 3-term. GATHER: rows via idx[0..*cnt).
// EPI: 0 = plain store (+z-slice offset), 3 = chain in-place (resid==C ok), 5 = proj (identity fast path).
constexpr int BM = 128, BN = 64, BK = 32;
constexpr int ALD = BK + 4;                 // 36
constexpr int ASZ = BM * ALD;               // 4608
constexpr int BSZ = BN * ALD;               // 2304

template <bool THREE, int EPI, bool GATHER>
__global__ void __launch_bounds__(256) gemm_tf32(
    const float* __restrict__ A, const float* __restrict__ Alo, int lda,
    const float* __restrict__ Bm, const float* __restrict__ Blo, int ldb,
    float* C, int ldc, int Kdim, int zstride,
    const float* resid,
    const float* __restrict__ gate, int gcol,
    float* __restrict__ Cr,
    const int* __restrict__ idx, const int* __restrict__ cnt)
{
    constexpr int NTA = THREE ? 2 : 1;
    constexpr int STAGE = NTA * (ASZ + BSZ);

    extern __shared__ float smem[];
    __shared__ int sidx[BM];

    const int tid = threadIdx.x;
    const int m0 = blockIdx.y * BM;
    const int n0 = blockIdx.x * BN;
    const int warp = tid >> 5;
    const int wm = warp >> 1;      // 0..3 -> 32-row slice
    const int wn = warp & 1;       // 0..1 -> 32-col slice
    const int koff = blockIdx.z * Kdim;

    if (EPI == 5) {
        if (g_notident == 0u) {    // proj == identity: copy resid tile
#pragma unroll
            for (int it = 0; it < 8; it++) {
                int e = it * 256 + tid;
                int r = e >> 4, c = (e & 15) << 2;
                size_t ix = (size_t)(m0 + r) * ldc + n0 + c;
                *(float4*)&C[ix] = *(const float4*)&resid[ix];
            }
            return;
        }
    }

    int n_act = 0;
    if (GATHER) {
        n_act = *cnt;
        if (m0 >= n_act) return;
        int m = m0 + tid;
        if (tid < BM) sidx[tid] = (m < n_act) ? idx[m] : idx[m0];
        __syncthreads();
    }

    wmma::fragment<wmma::accumulator, 16, 16, 8, float> acc[2][2];
#pragma unroll
    for (int i = 0; i < 2; i++)
#pragma unroll
        for (int j = 0; j < 2; j++) wmma::fill_fragment(acc[i][j], 0.0f);

    const int iters = Kdim / BK;

    auto load_stage = [&](int s, int k0) {
        float* as = smem + s * STAGE;
        float* al = as + ASZ;
        float* bs = as + NTA * ASZ;
        float* bl = bs + BSZ;
#pragma unroll
        for (int i = 0; i < 4; i++) {
            int e = i * 256 + tid;
            int r = e >> 3, c = (e & 7) << 2;
            int grow = GATHER ? sidx[r] : (m0 + r);
            cp16(&as[r * ALD + c], &A[(size_t)grow * lda + koff + k0 + c]);
            if (THREE) cp16(&al[r * ALD + c], &Alo[(size_t)grow * lda + koff + k0 + c]);
        }
#pragma unroll
        for (int i = 0; i < 2; i++) {
            int e = i * 256 + tid;
            int r = e >> 3, c = (e & 7) << 2;
            cp16(&bs[r * ALD + c], &Bm[(size_t)(n0 + r) * ldb + koff + k0 + c]);
            if (THREE) cp16(&bl[r * ALD + c], &Blo[(size_t)(n0 + r) * ldb + koff + k0 + c]);
        }
    };

    load_stage(0, 0);
    cp_commit();

    for (int it = 0; it < iters; it++) {
        if (it + 1 < iters) load_stage((it + 1) & 1, (it + 1) * BK);
        cp_commit();              // empty group on last iter keeps counts aligned
        cp_wait<1>();
        __syncthreads();

        const float* as = smem + (it & 1) * STAGE;
        const float* al = as + ASZ;
        const float* bs = as + NTA * ASZ;
        const float* bl = bs + BSZ;

#pragma unroll
        for (int kk = 0; kk < BK / 8; kk++) {
            wmma::fragment<wmma::matrix_a, 16, 16, 8, wmma::precision::tf32, wmma::row_major> af[2], afl[THREE ? 2 : 1];
            wmma::fragment<wmma::matrix_b, 16, 16, 8, wmma::precision::tf32, wmma::col_major> bf[2], bfl[THREE ? 2 : 1];
#pragma unroll
            for (int i = 0; i < 2; i++) {
                wmma::load_matrix_sync(af[i], &as[(wm * 32 + i * 16) * ALD + kk * 8], ALD);
                if (THREE)
                    wmma::load_matrix_sync(afl[i], &al[(wm * 32 + i * 16) * ALD + kk * 8], ALD);
            }
#pragma unroll
            for (int j = 0; j < 2; j++) {
                wmma::load_matrix_sync(bf[j], &bs[(wn * 32 + j * 16) * ALD + kk * 8], ALD);
                if (THREE)
                    wmma::load_matrix_sync(bfl[j], &bl[(wn * 32 + j * 16) * ALD + kk * 8], ALD);
            }
#pragma unroll
            for (int i = 0; i < 2; i++)
#pragma unroll
                for (int j = 0; j < 2; j++) {
                    if (THREE) {
                        wmma::mma_sync(acc[i][j], af[i], bfl[j], acc[i][j]);
                        wmma::mma_sync(acc[i][j], afl[i], bf[j], acc[i][j]);
                    }
                    wmma::mma_sync(acc[i][j], af[i], bf[j], acc[i][j]);
                }
        }
        __syncthreads();
    }

    // epilogue through smem, float4 global I/O
    constexpr int SLD = BN + 4;   // 68
    float* St = smem;
#pragma unroll
    for (int i = 0; i < 2; i++)
#pragma unroll
        for (int j = 0; j < 2; j++)
            wmma::store_matrix_sync(&St[(wm * 32 + i * 16) * SLD + wn * 32 + j * 16],
                                    acc[i][j], SLD, wmma::mem_row_major);
    __syncthreads();
#pragma unroll
    for (int it = 0; it < 8; it++) {
        int e = it * 256 + tid;
        int r = e >> 4, c = (e & 15) << 2;
        float4 v = *(const float4*)&St[r * SLD + c];
        int col = n0 + c;
        if (EPI == 3) {
            if (m0 + r >= n_act) continue;
            int grow = sidx[r];
            size_t ix = (size_t)grow * ldc + col;
            float g = gate[grow * NTASK + gcol];
            float4 rs = *(const float4*)&resid[ix];
            v.x = rs.x + g * v.x; v.y = rs.y + g * v.y;
            v.z = rs.z + g * v.z; v.w = rs.w + g * v.w;
            *(float4*)&C[ix] = v;                      // in-place fp32 x
            float4 t;
            t.x = wmma::__float_to_tf32(v.x); t.y = wmma::__float_to_tf32(v.y);
            t.z = wmma::__float_to_tf32(v.z); t.w = wmma::__float_to_tf32(v.w);
            *(float4*)&Cr[ix] = t;                     // next rounded buffer
        } else {
            size_t ix = (size_t)blockIdx.z * zstride + (size_t)(m0 + r) * ldc + col;
            *(float4*)&C[ix] = v;
        }
    }
}

// ---------------- G = W1 @ W1^T in exact fp32 (SIMT, smem-tiled) ----------------
__global__ void __launch_bounds__(256) gram_kernel(const float* __restrict__ W1)
{
    __shared__ float As[32][33], Bs[32][33];
    const int tid = threadIdx.x;
    const int r0 = blockIdx.y * 32, c0 = blockIdx.x * 32;
    const int ty = tid >> 4, tx = tid & 15;
    float a00 = 0.f, a01 = 0.f, a10 = 0.f, a11 = 0.f;

    for (int k0 = 0; k0 < FDIM; k0 += 32) {
#pragma unroll
        for (int i = 0; i < 4; i++) {
            int e = i * 256 + tid;
            int r = e >> 5, c = e & 31;
            As[r][c] = W1[(size_t)(r0 + r) * FDIM + k0 + c];
            Bs[r][c] = W1[(size_t)(c0 + r) * FDIM + k0 + c];
        }
        __syncthreads();
#pragma unroll 8
        for (int k = 0; k < 32; k++) {
            float x0 = As[ty * 2][k],     x1 = As[ty * 2 + 1][k];
            float y0 = Bs[tx * 2][k],     y1 = Bs[tx * 2 + 1][k];
            a00 = fmaf(x0, y0, a00); a01 = fmaf(x0, y1, a01);
            a10 = fmaf(x1, y0, a10); a11 = fmaf(x1, y1, a11);
        }
        __syncthreads();
    }
    int gr = r0 + ty * 2, gc = c0 + tx * 2;
    g_G[gr * HDIM + gc] = a00;       g_G[gr * HDIM + gc + 1] = a01;
    g_G[(gr + 1) * HDIM + gc] = a10; g_G[(gr + 1) * HDIM + gc + 1] = a11;
}

// ---------------- h reduce: h = part0 + part1 + b1 ----------------
__global__ void __launch_bounds__(256) hreduce_kernel(const float* __restrict__ b1)
{
    int e = blockIdx.x * 256 + threadIdx.x;          // one float4
    size_t ix = (size_t)e * 4;
    int col = (int)(ix & (HDIM - 1));
    float4 p0 = *(const float4*)&g_hpart[ix];
    float4 p1 = *(const float4*)&g_hpart[(size_t)BATCH * HDIM + ix];
    float4 v;
    v.x = p0.x + p1.x + b1[col];
    v.y = p0.y + p1.y + b1[col + 1];
    v.z = p0.z + p1.z + b1[col + 2];
    v.w = p0.w + p1.w + b1[col + 3];
    *(float4*)&g_h[ix] = v;
}

// ---------------- prep: tf32 splits (+ task transpose, + x init) ----------------
__global__ void __launch_bounds__(256) prep_kernel(
    const float* __restrict__ F, const float* __restrict__ T,
    const float* __restrict__ W1, const float* __restrict__ P)
{
    int b = blockIdx.x, tid = threadIdx.x;
    if (b < 8192) {
        __shared__ float s[32][33];
        int j = b >> 10, t = b & 1023;
        int tr = t >> 5, tc = t & 31;
        int x = tid & 31, y = tid >> 5;
        const float* src = T + (size_t)j * FDIM * FDIM;
#pragma unroll
        for (int i = 0; i < 4; i++)
            s[y + i * 8][x] = src[(size_t)(tr * 32 + y + i * 8) * FDIM + tc * 32 + x];
        __syncthreads();
        float* dh = g_Thi + (size_t)j * FDIM * FDIM;
#pragma unroll
        for (int i = 0; i < 4; i++) {
            int n = tc * 32 + y + i * 8, k = tr * 32 + x;
            dh[(size_t)n * FDIM + k] = wmma::__float_to_tf32(s[x][y + i * 8]);
        }
    } else if (b < 10240) {
        size_t base = (size_t)(b - 8192) * 4096 + tid * 16;
#pragma unroll
        for (int q = 0; q < 4; q++) {
            float4 v = *(const float4*)&F[base + q * 4];
            *(float4*)&g_xa[base + q * 4] = v;               // x init (in-place chain)
            float vv[4] = {v.x, v.y, v.z, v.w};
#pragma unroll
            for (int e = 0; e < 4; e++) {
                size_t ix = base + q * 4 + e;
                float hi = wmma::__float_to_tf32(vv[e]);
                g_fhi[ix] = hi;
                g_flo[ix] = wmma::__float_to_tf32(vv[e] - hi);
            }
        }
    } else if (b < 10304) {
        size_t base = (size_t)(b - 10240) * 4096 + tid * 16;
#pragma unroll
        for (int q = 0; q < 4; q++) {
            float4 v = *(const float4*)&W1[base + q * 4];
            float vv[4] = {v.x, v.y, v.z, v.w};
#pragma unroll
            for (int e = 0; e < 4; e++) {
                size_t ix = base + q * 4 + e;
                float hi = wmma::__float_to_tf32(vv[e]);
                g_W1hi[ix] = hi;
                g_W1lo[ix] = wmma::__float_to_tf32(vv[e] - hi);
            }
        }
    } else {
        size_t base = (size_t)(b - 10304) * 4096 + tid * 16;
#pragma unroll
        for (int q = 0; q < 4; q++) {
            float4 v = *(const float4*)&P[base + q * 4];
            float vv[4] = {v.x, v.y, v.z, v.w};
#pragma unroll
            for (int e = 0; e < 4; e++) {
                size_t ix = base + q * 4 + e;
                float hi = wmma::__float_to_tf32(vv[e]);
                g_Phi[ix] = hi;
                g_Plo[ix] = wmma::__float_to_tf32(vv[e] - hi);
            }
        }
    }
}

// ---------------- proj identity check ----------------
__global__ void projchk_kernel(const float* __restrict__ P)
{
    int e = blockIdx.x * 256 + threadIdx.x;
    int idx4 = e * 4;
    int row = idx4 >> 10;
    float4 v = *(const float4*)&P[idx4];
    float vv[4] = {v.x, v.y, v.z, v.w};
    bool bad = false;
#pragma unroll
    for (int q = 0; q < 4; q++) {
        int col = (idx4 + q) & 1023;
        float exp = (col == row) ? 1.0f : 0.0f;
        if (vv[q] != exp) bad = true;
    }
    if (__syncthreads_or(bad) && threadIdx.x == 0) atomicOr(&g_notident, 1u);
}

// ---------------- split final x into tf32 hi/lo (only if proj != I) ----------------
__global__ void __launch_bounds__(256) splitx_kernel(const float* __restrict__ X)
{
    if (g_notident == 0u) return;
    size_t base = (size_t)blockIdx.x * 4096 + threadIdx.x * 16;
#pragma unroll
    for (int q = 0; q < 4; q++) {
        float4 v = *(const float4*)&X[base + q * 4];
        float vv[4] = {v.x, v.y, v.z, v.w};
#pragma unroll
        for (int e = 0; e < 4; e++) {
            size_t ix = base + q * 4 + e;
            float hi = wmma::__float_to_tf32(vv[e]);
            g_fhi[ix] = hi;
            g_flo[ix] = wmma::__float_to_tf32(vv[e] - hi);
        }
    }
}

// ---------------- coeffs = relu(h) @ W2^T + b2 ----------------
__global__ void coeffs_kernel(const float* __restrict__ W2, const float* __restrict__ b2)
{
    int tid = threadIdx.x;
    int row = blockIdx.x * 32 + (tid >> 3);
    int k = tid & 7;
    const float* hr = g_h + (size_t)row * HDIM;
    const float* w = W2 + k * HDIM;
    float s = b2[k];
#pragma unroll 8
    for (int h = 0; h < HDIM; h++) s += fmaxf(hr[h], 0.0f) * w[h];
    g_coeffs[row * NTASK + k] = s;
}

// ---------------- unc^2[b,k] = a^T G a ----------------
__global__ void __launch_bounds__(256) unc_kernel(const float* __restrict__ W2)
{
    __shared__ float W2s[NTASK * HDIM];
    __shared__ float Gs[HDIM * 32];
    int tid = threadIdx.x, lane = tid & 31, warp = tid >> 5;
    for (int i = tid; i < NTASK * HDIM; i += 256) W2s[i] = W2[i];

    int row = blockIdx.x * 8 + warp;
    const float* hr = g_h + (size_t)row * HDIM;
    unsigned mb[8];
#pragma unroll
    for (int j = 0; j < 8; j++)
        mb[j] = __ballot_sync(0xffffffffu, hr[j * 32 + lane] > 0.0f);

    float u2[8];
#pragma unroll
    for (int k = 0; k < 8; k++) u2[k] = 0.0f;

    for (int c = 0; c < 8; c++) {
        __syncthreads();
        for (int i = tid; i < HDIM * 32; i += 256) {
            int h = i >> 5, l = i & 31;
            Gs[i] = g_G[h * HDIM + c * 32 + l];
        }
        __syncthreads();
        float t[8];
#pragma unroll
        for (int k = 0; k < 8; k++) t[k] = 0.0f;
        for (int h = 0; h < HDIM; h++) {
            if ((mb[h >> 5] >> (h & 31)) & 1u) {
                float gv = Gs[h * 32 + lane];
#pragma unroll
                for (int k = 0; k < 8; k++) t[k] += W2s[k * HDIM + h] * gv;
            }
        }
        int hp = c * 32 + lane;
        if ((mb[hp >> 5] >> (hp & 31)) & 1u) {
#pragma unroll
            for (int k = 0; k < 8; k++) u2[k] += W2s[k * HDIM + hp] * t[k];
        }
    }
#pragma unroll
    for (int k = 0; k < 8; k++) {
        float v = u2[k];
        for (int off = 16; off; off >>= 1) v += __shfl_down_sync(0xffffffffu, v, off);
        if (lane == 0) {
            v = fmaxf(v, 0.0f);
            g_unc2[row * NTASK + k] = v;
            atomicMax(&g_max2bits, __float_as_uint(v));
        }
    }
}

// ---------------- gating + active-row compaction ----------------
__global__ void gate_kernel(const float* __restrict__ bthr, const float* __restrict__ beta)
{
    int i = blockIdx.x * blockDim.x + threadIdx.x;
    if (i >= BATCH * NTASK) return;
    int row = i >> 3, k = i & 7;
    float max2 = __uint_as_float(g_max2bits);
    float u = (max2 > 0.0f) ? sqrtf(g_unc2[i] / max2) : sqrtf(g_unc2[i]);
    float base = log1pf(expf(bthr[0]));
    float thr = base * (1.0f + fmaxf(beta[0], 0.0f) * u);
    float cf = g_coeffs[i];
    float gf = (fabsf(cf) < thr) ? 0.0f : cf;
    g_gated[i] = gf;
    if (gf != 0.0f) {
        int p = atomicAdd(&g_cnt[k], 1);
        g_idx[k * BATCH + p] = row;
    }
}

// ---------------- copy rounded buffer for zero-gate rows ----------------
__global__ void __launch_bounds__(256) copy_round_inactive(
    const float* __restrict__ rin, float* __restrict__ rout, int j)
{
    int row = blockIdx.x;
    if (g_gated[row * NTASK + j] != 0.0f) return;
    size_t b4 = (size_t)row * (FDIM / 4) + threadIdx.x;
    ((float4*)rout)[b4] = ((const float4*)rin)[b4];
}

// ---------------- launch ----------------
extern "C" void kernel_launch(void* const* d_in, const int* in_sizes, int n_in,
                              void* d_out, int out_size)
{
    const float* features = (const float*)d_in[0];
    const float* W1   = (const float*)d_in[1];
    const float* b1   = (const float*)d_in[2];
    const float* W2   = (const float*)d_in[3];
    const float* b2   = (const float*)d_in[4];
    const float* task = (const float*)d_in[5];
    const float* projW = (const float*)d_in[6];
    const float* bthr = (const float*)d_in[7];
    const float* beta = (const float*)d_in[8];
    float* out = (float*)d_out;

    float *fhi, *flo, *w1hi, *w1lo, *thi, *phi, *plo;
    float *xa, *xar, *xbr, *hpart, *gated;
    int *idxp, *cntp;
    void *maxp, *nip;
    cudaGetSymbolAddress((void**)&fhi, g_fhi);   cudaGetSymbolAddress((void**)&flo, g_flo);
    cudaGetSymbolAddress((void**)&w1hi, g_W1hi); cudaGetSymbolAddress((void**)&w1lo, g_W1lo);
    cudaGetSymbolAddress((void**)&thi, g_Thi);
    cudaGetSymbolAddress((void**)&phi, g_Phi);   cudaGetSymbolAddress((void**)&plo, g_Plo);
    cudaGetSymbolAddress((void**)&xa, g_xa);
    cudaGetSymbolAddress((void**)&xar, g_xar);   cudaGetSymbolAddress((void**)&xbr, g_xbr);
    cudaGetSymbolAddress((void**)&hpart, g_hpart);
    cudaGetSymbolAddress((void**)&gated, g_gated);
    cudaGetSymbolAddress((void**)&idxp, g_idx);  cudaGetSymbolAddress((void**)&cntp, g_cnt);
    cudaGetSymbolAddress(&maxp, g_max2bits);     cudaGetSymbolAddress(&nip, g_notident);

    const int smem1 = 2 * (ASZ + BSZ) * 4;           // 55296
    const int smem3 = 2 * 2 * (ASZ + BSZ) * 4;       // 110592
    cudaFuncSetAttribute(gemm_tf32<true,  0, false>, cudaFuncAttributeMaxDynamicSharedMemorySize, smem3);
    cudaFuncSetAttribute(gemm_tf32<true,  5, false>, cudaFuncAttributeMaxDynamicSharedMemorySize, smem3);
    cudaFuncSetAttribute(gemm_tf32<false, 3, true >, cudaFuncAttributeMaxDynamicSharedMemorySize, smem1);

    cudaMemsetAsync(maxp, 0, 4);
    cudaMemsetAsync(cntp, 0, NTASK * sizeof(int));
    cudaMemsetAsync(nip, 0, 4);

    // (1) prep (+x init) and proj identity check
    prep_kernel<<<10560, 256>>>(features, task, W1, projW);
    projchk_kernel<<<1024, 256>>>(projW);

    // (2) G = W1 @ W1^T  exact fp32 SIMT
    gram_kernel<<<dim3(8, 8), 256>>>(W1);

    // (3) h partials: F @ W1^T, split-K=2 (3-term tf32), then fixed-order reduce
    gemm_tf32<true, 0, false><<<dim3(HDIM / BN, BATCH / BM, 2), 256, smem3>>>(
        fhi, flo, FDIM, w1hi, w1lo, FDIM, hpart, HDIM, FDIM / 2, BATCH * HDIM,
        nullptr, nullptr, 0, nullptr, nullptr, nullptr);
    hreduce_kernel<<<BATCH * HDIM / 1024, 256>>>(b1);

    // (4-6) coeffs, unc, gate+compact
    coeffs_kernel<<<BATCH / 32, 256>>>(W2, b2);
    unc_kernel<<<BATCH / 8, 256>>>(W2);
    gate_kernel<<<(BATCH * NTASK + 255) / 256, 256>>>(bthr, beta);

    // (7..) chain: in-place fp32 x, gathered GEMM over active rows, rounded ping-pong
    dim3 gX(FDIM / BN, BATCH / BM);      // 16 x 64
    const float* around = fhi;           // rounded features
    float* nextr = xar;
    for (int j = 0; j < NTASK; j++) {
        copy_round_inactive<<<BATCH, 256>>>(around, nextr, j);
        gemm_tf32<false, 3, true><<<gX, 256, smem1>>>(
            around, nullptr, FDIM, thi + (size_t)j * FDIM * FDIM, nullptr, FDIM,
            xa, FDIM, FDIM, 0, xa, gated, j, nextr,
            idxp + j * BATCH, cntp + j);
        around = nextr;
        nextr = (around == xar) ? xbr : xar;
    }

    // final split (no-op when proj == I)
    splitx_kernel<<<BATCH * FDIM / 4096, 256>>>(xa);

    // proj: identity -> copy, else 3-term GEMM
    gemm_tf32<true, 5, false><<<gX, 256, smem3>>>(
        fhi, flo, FDIM, phi, plo, FDIM, out, FDIM, FDIM, 0,
        xa, nullptr, 0, nullptr, nullptr, nullptr);
}

// round 10
// speedup vs baseline: 2.8844x; 1.0100x over previous
#include <cuda_runtime.h>
#include <mma.h>
#include <cstdint>
#include <cstddef>

using namespace nvcuda;

#define BATCH 8192
#define FDIM  1024
#define HDIM  256
#define NTASK 8

// ---------------- scratch (static device globals; no allocation) ----------------
__device__ float g_fhi[BATCH * FDIM], g_flo[BATCH * FDIM];   // features tf32 split; reused for final-x split
__device__ float g_W1hi[HDIM * FDIM], g_W1lo[HDIM * FDIM];
__device__ float g_Thi[NTASK * FDIM * FDIM];                 // task mats transposed to [N,K], tf32
__device__ float g_Phi[FDIM * FDIM], g_Plo[FDIM * FDIM];     // projW split ([N,K] layout already)
__device__ float g_xa[BATCH * FDIM];                         // chain x, updated IN PLACE
__device__ float g_xar[BATCH * FDIM], g_xbr[BATCH * FDIM];   // tf32-rounded x ping-pong (A operand)
__device__ float g_hpart[2 * BATCH * HDIM];                  // h split-K partials
__device__ float    g_h[BATCH * HDIM];
__device__ float    g_G[HDIM * HDIM];
__device__ float    g_coeffs[BATCH * NTASK];
__device__ float    g_unc2[BATCH * NTASK];
__device__ unsigned g_max2bits;
__device__ float    g_gated[BATCH * NTASK];
__device__ int      g_cnt[NTASK];
__device__ int      g_idx[NTASK * BATCH];
__device__ unsigned g_notident;

// ---------------- cp.async helpers ----------------
__device__ __forceinline__ void cp16(float* s, const float* g) {
    unsigned sa = (unsigned)__cvta_generic_to_shared(s);
    asm volatile("cp.async.cg.shared.global [%0], [%1], 16;" :: "r"(sa), "l"(g));
}
__device__ __forceinline__ void cp_commit() { asm volatile("cp.async.commit_group;"); }
template <int N> __device__ __forceinline__ void cp_wait() {
    asm volatile("cp.async.wait_group %0;" :: "n"(N));
}

// ---------------- tf32 GEMM: C[M,N] = A[M,K] @ B[N,K]^T ----------------
// 256 threads (8 warps, 32x32 warp tiles), 128x64xBKT CTA tile, cp.async double buffer.
// __launch_bounds__(256,2): regs capped so 2 CTAs/SM fit. THREE uses BKT=16 so smem fits 2/SM too.
// Operands PRE-ROUNDED to tf32 -> no cvt in inner loop.
// EPI: 0 = plain store (+z-slice offset), 3 = chain in-place gathered, 5 = proj (identity fast path).
constexpr int BM = 128, BN = 64;

template <int BKT, bool THREE, int EPI, bool GATHER>
__global__ void __launch_bounds__(256, 2) gemm_tf32(
    const float* __restrict__ A, const float* __restrict__ Alo, int lda,
    const float* __restrict__ Bm, const float* __restrict__ Blo, int ldb,
    float* C, int ldc, int Kdim, int zstride,
    const float* resid,
    const float* __restrict__ gate, int gcol,
    float* __restrict__ Cr,
    const int* __restrict__ idx, const int* __restrict__ cnt)
{
    constexpr int ALD = BKT + 4;
    constexpr int ASZ = BM * ALD;
    constexpr int BSZ = BN * ALD;
    constexpr int NTA = THREE ? 2 : 1;
    constexpr int STAGE = NTA * (ASZ + BSZ);
    constexpr int AQ = BKT / 4;                 // float4 per A/B row
    constexpr int AIT = BM * AQ / 256;          // A-tile cp16 iters per thread
    constexpr int BIT = BN * AQ / 256;          // B-tile cp16 iters per thread

    extern __shared__ float smem[];
    __shared__ int sidx[BM];

    const int tid = threadIdx.x;
    const int m0 = blockIdx.y * BM;
    const int n0 = blockIdx.x * BN;
    const int warp = tid >> 5;
    const int wm = warp >> 1;      // 0..3 -> 32-row slice
    const int wn = warp & 1;       // 0..1 -> 32-col slice
    const int koff = blockIdx.z * Kdim;

    if (EPI == 5) {
        if (g_notident == 0u) {    // proj == identity: copy resid tile
#pragma unroll
            for (int it = 0; it < 8; it++) {
                int e = it * 256 + tid;
                int r = e >> 4, c = (e & 15) << 2;
                size_t ix = (size_t)(m0 + r) * ldc + n0 + c;
                *(float4*)&C[ix] = *(const float4*)&resid[ix];
            }
            return;
        }
    }

    int n_act = 0;
    if (GATHER) {
        n_act = *cnt;
        if (m0 >= n_act) return;
        int m = m0 + tid;
        if (tid < BM) sidx[tid] = (m < n_act) ? idx[m] : idx[m0];
        __syncthreads();
    }

    wmma::fragment<wmma::accumulator, 16, 16, 8, float> acc[2][2];
#pragma unroll
    for (int i = 0; i < 2; i++)
#pragma unroll
        for (int j = 0; j < 2; j++) wmma::fill_fragment(acc[i][j], 0.0f);

    const int iters = Kdim / BKT;

    auto load_stage = [&](int s, int k0) {
        float* as = smem + s * STAGE;
        float* al = as + ASZ;
        float* bs = as + NTA * ASZ;
        float* bl = bs + BSZ;
#pragma unroll
        for (int i = 0; i < AIT; i++) {
            int e = i * 256 + tid;
            int r = e / AQ, c = (e % AQ) << 2;
            int grow = GATHER ? sidx[r] : (m0 + r);
            cp16(&as[r * ALD + c], &A[(size_t)grow * lda + koff + k0 + c]);
            if (THREE) cp16(&al[r * ALD + c], &Alo[(size_t)grow * lda + koff + k0 + c]);
        }
#pragma unroll
        for (int i = 0; i < BIT; i++) {
            int e = i * 256 + tid;
            int r = e / AQ, c = (e % AQ) << 2;
            cp16(&bs[r * ALD + c], &Bm[(size_t)(n0 + r) * ldb + koff + k0 + c]);
            if (THREE) cp16(&bl[r * ALD + c], &Blo[(size_t)(n0 + r) * ldb + koff + k0 + c]);
        }
    };

    load_stage(0, 0);
    cp_commit();

    for (int it = 0; it < iters; it++) {
        if (it + 1 < iters) load_stage((it + 1) & 1, (it + 1) * BKT);
        cp_commit();              // empty group on last iter keeps counts aligned
        cp_wait<1>();
        __syncthreads();

        const float* as = smem + (it & 1) * STAGE;
        const float* al = as + ASZ;
        const float* bs = as + NTA * ASZ;
        const float* bl = bs + BSZ;

#pragma unroll
        for (int kk = 0; kk < BKT / 8; kk++) {
            wmma::fragment<wmma::matrix_a, 16, 16, 8, wmma::precision::tf32, wmma::row_major> af[2], afl[THREE ? 2 : 1];
            wmma::fragment<wmma::matrix_b, 16, 16, 8, wmma::precision::tf32, wmma::col_major> bf[2], bfl[THREE ? 2 : 1];
#pragma unroll
            for (int i = 0; i < 2; i++) {
                wmma::load_matrix_sync(af[i], &as[(wm * 32 + i * 16) * ALD + kk * 8], ALD);
                if (THREE)
                    wmma::load_matrix_sync(afl[i], &al[(wm * 32 + i * 16) * ALD + kk * 8], ALD);
            }
#pragma unroll
            for (int j = 0; j < 2; j++) {
                wmma::load_matrix_sync(bf[j], &bs[(wn * 32 + j * 16) * ALD + kk * 8], ALD);
                if (THREE)
                    wmma::load_matrix_sync(bfl[j], &bl[(wn * 32 + j * 16) * ALD + kk * 8], ALD);
            }
#pragma unroll
            for (int i = 0; i < 2; i++)
#pragma unroll
                for (int j = 0; j < 2; j++) {
                    if (THREE) {
                        wmma::mma_sync(acc[i][j], af[i], bfl[j], acc[i][j]);
                        wmma::mma_sync(acc[i][j], afl[i], bf[j], acc[i][j]);
                    }
                    wmma::mma_sync(acc[i][j], af[i], bf[j], acc[i][j]);
                }
        }
        __syncthreads();
    }

    // epilogue through smem, float4 global I/O
    constexpr int SLD = BN + 4;   // 68
    float* St = smem;
#pragma unroll
    for (int i = 0; i < 2; i++)
#pragma unroll
        for (int j = 0; j < 2; j++)
            wmma::store_matrix_sync(&St[(wm * 32 + i * 16) * SLD + wn * 32 + j * 16],
                                    acc[i][j], SLD, wmma::mem_row_major);
    __syncthreads();
#pragma unroll
    for (int it = 0; it < 8; it++) {
        int e = it * 256 + tid;
        int r = e >> 4, c = (e & 15) << 2;
        float4 v = *(const float4*)&St[r * SLD + c];
        int col = n0 + c;
        if (EPI == 3) {
            if (m0 + r >= n_act) continue;
            int grow = sidx[r];
            size_t ix = (size_t)grow * ldc + col;
            float g = gate[grow * NTASK + gcol];
            float4 rs = *(const float4*)&resid[ix];
            v.x = rs.x + g * v.x; v.y = rs.y + g * v.y;
            v.z = rs.z + g * v.z; v.w = rs.w + g * v.w;
            *(float4*)&C[ix] = v;                      // in-place fp32 x
            float4 t;
            t.x = wmma::__float_to_tf32(v.x); t.y = wmma::__float_to_tf32(v.y);
            t.z = wmma::__float_to_tf32(v.z); t.w = wmma::__float_to_tf32(v.w);
            *(float4*)&Cr[ix] = t;                     // next rounded buffer
        } else {
            size_t ix = (size_t)blockIdx.z * zstride + (size_t)(m0 + r) * ldc + col;
            *(float4*)&C[ix] = v;
        }
    }
}

// ---------------- G = W1 @ W1^T in exact fp32 (SIMT, smem-tiled) ----------------
__global__ void __launch_bounds__(256) gram_kernel(const float* __restrict__ W1)
{
    __shared__ float As[32][33], Bs[32][33];
    const int tid = threadIdx.x;
    const int r0 = blockIdx.y * 32, c0 = blockIdx.x * 32;
    const int ty = tid >> 4, tx = tid & 15;
    float a00 = 0.f, a01 = 0.f, a10 = 0.f, a11 = 0.f;

    for (int k0 = 0; k0 < FDIM; k0 += 32) {
#pragma unroll
        for (int i = 0; i < 4; i++) {
            int e = i * 256 + tid;
            int r = e >> 5, c = e & 31;
            As[r][c] = W1[(size_t)(r0 + r) * FDIM + k0 + c];
            Bs[r][c] = W1[(size_t)(c0 + r) * FDIM + k0 + c];
        }
        __syncthreads();
#pragma unroll 8
        for (int k = 0; k < 32; k++) {
            float x0 = As[ty * 2][k],     x1 = As[ty * 2 + 1][k];
            float y0 = Bs[tx * 2][k],     y1 = Bs[tx * 2 + 1][k];
            a00 = fmaf(x0, y0, a00); a01 = fmaf(x0, y1, a01);
            a10 = fmaf(x1, y0, a10); a11 = fmaf(x1, y1, a11);
        }
        __syncthreads();
    }
    int gr = r0 + ty * 2, gc = c0 + tx * 2;
    g_G[gr * HDIM + gc] = a00;       g_G[gr * HDIM + gc + 1] = a01;
    g_G[(gr + 1) * HDIM + gc] = a10; g_G[(gr + 1) * HDIM + gc + 1] = a11;
}

// ---------------- h reduce: h = part0 + part1 + b1 ----------------
__global__ void __launch_bounds__(256) hreduce_kernel(const float* __restrict__ b1)
{
    int e = blockIdx.x * 256 + threadIdx.x;          // one float4
    size_t ix = (size_t)e * 4;
    int col = (int)(ix & (HDIM - 1));
    float4 p0 = *(const float4*)&g_hpart[ix];
    float4 p1 = *(const float4*)&g_hpart[(size_t)BATCH * HDIM + ix];
    float4 v;
    v.x = p0.x + p1.x + b1[col];
    v.y = p0.y + p1.y + b1[col + 1];
    v.z = p0.z + p1.z + b1[col + 2];
    v.w = p0.w + p1.w + b1[col + 3];
    *(float4*)&g_h[ix] = v;
}

// ---------------- prep: tf32 splits (+ task transpose, + x init) ----------------
__global__ void __launch_bounds__(256) prep_kernel(
    const float* __restrict__ F, const float* __restrict__ T,
    const float* __restrict__ W1, const float* __restrict__ P)
{
    int b = blockIdx.x, tid = threadIdx.x;
    if (b < 8192) {
        __shared__ float s[32][33];
        int j = b >> 10, t = b & 1023;
        int tr = t >> 5, tc = t & 31;
        int x = tid & 31, y = tid >> 5;
        const float* src = T + (size_t)j * FDIM * FDIM;
#pragma unroll
        for (int i = 0; i < 4; i++)
            s[y + i * 8][x] = src[(size_t)(tr * 32 + y + i * 8) * FDIM + tc * 32 + x];
        __syncthreads();
        float* dh = g_Thi + (size_t)j * FDIM * FDIM;
#pragma unroll
        for (int i = 0; i < 4; i++) {
            int n = tc * 32 + y + i * 8, k = tr * 32 + x;
            dh[(size_t)n * FDIM + k] = wmma::__float_to_tf32(s[x][y + i * 8]);
        }
    } else if (b < 10240) {
        size_t base = (size_t)(b - 8192) * 4096 + tid * 16;
#pragma unroll
        for (int q = 0; q < 4; q++) {
            float4 v = *(const float4*)&F[base + q * 4];
            *(float4*)&g_xa[base + q * 4] = v;               // x init (in-place chain)
            float vv[4] = {v.x, v.y, v.z, v.w};
#pragma unroll
            for (int e = 0; e < 4; e++) {
                size_t ix = base + q * 4 + e;
                float hi = wmma::__float_to_tf32(vv[e]);
                g_fhi[ix] = hi;
                g_flo[ix] = wmma::__float_to_tf32(vv[e] - hi);
            }
        }
    } else if (b < 10304) {
        size_t base = (size_t)(b - 10240) * 4096 + tid * 16;
#pragma unroll
        for (int q = 0; q < 4; q++) {
            float4 v = *(const float4*)&W1[base + q * 4];
            float vv[4] = {v.x, v.y, v.z, v.w};
#pragma unroll
            for (int e = 0; e < 4; e++) {
                size_t ix = base + q * 4 + e;
                float hi = wmma::__float_to_tf32(vv[e]);
                g_W1hi[ix] = hi;
                g_W1lo[ix] = wmma::__float_to_tf32(vv[e] - hi);
            }
        }
    } else {
        size_t base = (size_t)(b - 10304) * 4096 + tid * 16;
#pragma unroll
        for (int q = 0; q < 4; q++) {
            float4 v = *(const float4*)&P[base + q * 4];
            float vv[4] = {v.x, v.y, v.z, v.w};
#pragma unroll
            for (int e = 0; e < 4; e++) {
                size_t ix = base + q * 4 + e;
                float hi = wmma::__float_to_tf32(vv[e]);
                g_Phi[ix] = hi;
                g_Plo[ix] = wmma::__float_to_tf32(vv[e] - hi);
            }
        }
    }
}

// ---------------- proj identity check ----------------
__global__ void projchk_kernel(const float* __restrict__ P)
{
    int e = blockIdx.x * 256 + threadIdx.x;
    int idx4 = e * 4;
    int row = idx4 >> 10;
    float4 v = *(const float4*)&P[idx4];
    float vv[4] = {v.x, v.y, v.z, v.w};
    bool bad = false;
#pragma unroll
    for (int q = 0; q < 4; q++) {
        int col = (idx4 + q) & 1023;
        float exp = (col == row) ? 1.0f : 0.0f;
        if (vv[q] != exp) bad = true;
    }
    if (__syncthreads_or(bad) && threadIdx.x == 0) atomicOr(&g_notident, 1u);
}

// ---------------- split final x into tf32 hi/lo (only if proj != I) ----------------
__global__ void __launch_bounds__(256) splitx_kernel(const float* __restrict__ X)
{
    if (g_notident == 0u) return;
    size_t base = (size_t)blockIdx.x * 4096 + threadIdx.x * 16;
#pragma unroll
    for (int q = 0; q < 4; q++) {
        float4 v = *(const float4*)&X[base + q * 4];
        float vv[4] = {v.x, v.y, v.z, v.w};
#pragma unroll
        for (int e = 0; e < 4; e++) {
            size_t ix = base + q * 4 + e;
            float hi = wmma::__float_to_tf32(vv[e]);
            g_fhi[ix] = hi;
            g_flo[ix] = wmma::__float_to_tf32(vv[e] - hi);
        }
    }
}

// ---------------- coeffs = relu(h) @ W2^T + b2 ----------------
__global__ void coeffs_kernel(const float* __restrict__ W2, const float* __restrict__ b2)
{
    int tid = threadIdx.x;
    int row = blockIdx.x * 32 + (tid >> 3);
    int k = tid & 7;
    const float* hr = g_h + (size_t)row * HDIM;
    const float* w = W2 + k * HDIM;
    float s = b2[k];
#pragma unroll 8
    for (int h = 0; h < HDIM; h++) s += fmaxf(hr[h], 0.0f) * w[h];
    g_coeffs[row * NTASK + k] = s;
}

// ---------------- unc^2[b,k] = a^T G a ----------------
__global__ void __launch_bounds__(256) unc_kernel(const float* __restrict__ W2)
{
    __shared__ float W2s[NTASK * HDIM];
    __shared__ float Gs[HDIM * 32];
    int tid = threadIdx.x, lane = tid & 31, warp = tid >> 5;
    for (int i = tid; i < NTASK * HDIM; i += 256) W2s[i] = W2[i];

    int row = blockIdx.x * 8 + warp;
    const float* hr = g_h + (size_t)row * HDIM;
    unsigned mb[8];
#pragma unroll
    for (int j = 0; j < 8; j++)
        mb[j] = __ballot_sync(0xffffffffu, hr[j * 32 + lane] > 0.0f);

    float u2[8];
#pragma unroll
    for (int k = 0; k < 8; k++) u2[k] = 0.0f;

    for (int c = 0; c < 8; c++) {
        __syncthreads();
        for (int i = tid; i < HDIM * 32; i += 256) {
            int h = i >> 5, l = i & 31;
            Gs[i] = g_G[h * HDIM + c * 32 + l];
        }
        __syncthreads();
        float t[8];
#pragma unroll
        for (int k = 0; k < 8; k++) t[k] = 0.0f;
        for (int h = 0; h < HDIM; h++) {
            if ((mb[h >> 5] >> (h & 31)) & 1u) {
                float gv = Gs[h * 32 + lane];
#pragma unroll
                for (int k = 0; k < 8; k++) t[k] += W2s[k * HDIM + h] * gv;
            }
        }
        int hp = c * 32 + lane;
        if ((mb[hp >> 5] >> (hp & 31)) & 1u) {
#pragma unroll
            for (int k = 0; k < 8; k++) u2[k] += W2s[k * HDIM + hp] * t[k];
        }
    }
#pragma unroll
    for (int k = 0; k < 8; k++) {
        float v = u2[k];
        for (int off = 16; off; off >>= 1) v += __shfl_down_sync(0xffffffffu, v, off);
        if (lane == 0) {
            v = fmaxf(v, 0.0f);
            g_unc2[row * NTASK + k] = v;
            atomicMax(&g_max2bits, __float_as_uint(v));
        }
    }
}

// ---------------- gating + active-row compaction ----------------
__global__ void gate_kernel(const float* __restrict__ bthr, const float* __restrict__ beta)
{
    int i = blockIdx.x * blockDim.x + threadIdx.x;
    if (i >= BATCH * NTASK) return;
    int row = i >> 3, k = i & 7;
    float max2 = __uint_as_float(g_max2bits);
    float u = (max2 > 0.0f) ? sqrtf(g_unc2[i] / max2) : sqrtf(g_unc2[i]);
    float base = log1pf(expf(bthr[0]));
    float thr = base * (1.0f + fmaxf(beta[0], 0.0f) * u);
    float cf = g_coeffs[i];
    float gf = (fabsf(cf) < thr) ? 0.0f : cf;
    g_gated[i] = gf;
    if (gf != 0.0f) {
        int p = atomicAdd(&g_cnt[k], 1);
        g_idx[k * BATCH + p] = row;
    }
}

// ---------------- copy rounded buffer for zero-gate rows ----------------
__global__ void __launch_bounds__(256) copy_round_inactive(
    const float* __restrict__ rin, float* __restrict__ rout, int j)
{
    int row = blockIdx.x;
    if (g_gated[row * NTASK + j] != 0.0f) return;
    size_t b4 = (size_t)row * (FDIM / 4) + threadIdx.x;
    ((float4*)rout)[b4] = ((const float4*)rin)[b4];
}

// ---------------- launch ----------------
extern "C" void kernel_launch(void* const* d_in, const int* in_sizes, int n_in,
                              void* d_out, int out_size)
{
    const float* features = (const float*)d_in[0];
    const float* W1   = (const float*)d_in[1];
    const float* b1   = (const float*)d_in[2];
    const float* W2   = (const float*)d_in[3];
    const float* b2   = (const float*)d_in[4];
    const float* task = (const float*)d_in[5];
    const float* projW = (const float*)d_in[6];
    const float* bthr = (const float*)d_in[7];
    const float* beta = (const float*)d_in[8];
    float* out = (float*)d_out;

    float *fhi, *flo, *w1hi, *w1lo, *thi, *phi, *plo;
    float *xa, *xar, *xbr, *hpart, *gated;
    int *idxp, *cntp;
    void *maxp, *nip;
    cudaGetSymbolAddress((void**)&fhi, g_fhi);   cudaGetSymbolAddress((void**)&flo, g_flo);
    cudaGetSymbolAddress((void**)&w1hi, g_W1hi); cudaGetSymbolAddress((void**)&w1lo, g_W1lo);
    cudaGetSymbolAddress((void**)&thi, g_Thi);
    cudaGetSymbolAddress((void**)&phi, g_Phi);   cudaGetSymbolAddress((void**)&plo, g_Plo);
    cudaGetSymbolAddress((void**)&xa, g_xa);
    cudaGetSymbolAddress((void**)&xar, g_xar);   cudaGetSymbolAddress((void**)&xbr, g_xbr);
    cudaGetSymbolAddress((void**)&hpart, g_hpart);
    cudaGetSymbolAddress((void**)&gated, g_gated);
    cudaGetSymbolAddress((void**)&idxp, g_idx);  cudaGetSymbolAddress((void**)&cntp, g_cnt);
    cudaGetSymbolAddress(&maxp, g_max2bits);     cudaGetSymbolAddress(&nip, g_notident);

    // smem sizes: THREE/BK=16: 2 stages * 2*(128*20 + 64*20) floats = 61440 B
    //             1-term/BK=32: 2 stages * (128*36 + 64*36) floats  = 55296 B
    //             THREE/BK=32 (proj fallback): 110592 B
    const int smem_h  = 2 * 2 * (BM * 20 + BN * 20) * 4;
    const int smem_c  = 2 * (BM * 36 + BN * 36) * 4;
    const int smem_p  = 2 * 2 * (BM * 36 + BN * 36) * 4;
    cudaFuncSetAttribute(gemm_tf32<16, true,  0, false>, cudaFuncAttributeMaxDynamicSharedMemorySize, smem_h);
    cudaFuncSetAttribute(gemm_tf32<32, true,  5, false>, cudaFuncAttributeMaxDynamicSharedMemorySize, smem_p);
    cudaFuncSetAttribute(gemm_tf32<32, false, 3, true >, cudaFuncAttributeMaxDynamicSharedMemorySize, smem_c);

    cudaMemsetAsync(maxp, 0, 4);
    cudaMemsetAsync(cntp, 0, NTASK * sizeof(int));
    cudaMemsetAsync(nip, 0, 4);

    // (1) prep (+x init) and proj identity check
    prep_kernel<<<10560, 256>>>(features, task, W1, projW);
    projchk_kernel<<<1024, 256>>>(projW);

    // (2) G = W1 @ W1^T  exact fp32 SIMT
    gram_kernel<<<dim3(8, 8), 256>>>(W1);

    // (3) h partials: F @ W1^T, split-K=2 (3-term tf32, BK=16), fixed-order reduce
    gemm_tf32<16, true, 0, false><<<dim3(HDIM / BN, BATCH / BM, 2), 256, smem_h>>>(
        fhi, flo, FDIM, w1hi, w1lo, FDIM, hpart, HDIM, FDIM / 2, BATCH * HDIM,
        nullptr, nullptr, 0, nullptr, nullptr, nullptr);
    hreduce_kernel<<<BATCH * HDIM / 1024, 256>>>(b1);

    // (4-6) coeffs, unc, gate+compact
    coeffs_kernel<<<BATCH / 32, 256>>>(W2, b2);
    unc_kernel<<<BATCH / 8, 256>>>(W2);
    gate_kernel<<<(BATCH * NTASK + 255) / 256, 256>>>(bthr, beta);

    // (7..) chain: in-place fp32 x, gathered GEMM over active rows, rounded ping-pong
    dim3 gX(FDIM / BN, BATCH / BM);      // 16 x 64
    const float* around = fhi;           // rounded features
    float* nextr = xar;
    for (int j = 0; j < NTASK; j++) {
        copy_round_inactive<<<BATCH, 256>>>(around, nextr, j);
        gemm_tf32<32, false, 3, true><<<gX, 256, smem_c>>>(
            around, nullptr, FDIM, thi + (size_t)j * FDIM * FDIM, nullptr, FDIM,
            xa, FDIM, FDIM, 0, xa, gated, j, nextr,
            idxp + j * BATCH, cntp + j);
        around = nextr;
        nextr = (around == xar) ? xbr : xar;
    }

    // final split (no-op when proj == I)
    splitx_kernel<<<BATCH * FDIM / 4096, 256>>>(xa);

    // proj: identity -> copy, else 3-term GEMM
    gemm_tf32<32, true, 5, false><<<gX, 256, smem_p>>>(
        fhi, flo, FDIM, phi, plo, FDIM, out, FDIM, FDIM, 0,
        xa, nullptr, 0, nullptr, nullptr, nullptr);
}